// round 1
// baseline (speedup 1.0000x reference)
#include <cuda_runtime.h>
#include <cuda_bf16.h>
#include <math.h>

// ---------------------------------------------------------------------------
// Problem constants: B=2, S=2048, D=1024, H=16, head_dim=64, rope dims=32
// ---------------------------------------------------------------------------
#define BV 2
#define HV 16
#define SV 2048
#define DV 1024
#define KD 64          // head dim
#define MROWS (BV*SV)  // 4096

// Scratch (device globals: allocation-free rule)
__device__ float g_q[MROWS * DV];
__device__ float g_k[MROWS * DV];
__device__ float g_v[MROWS * DV];
__device__ float g_y[MROWS * DV];

// ---------------------------------------------------------------------------
// SGEMM: C[M,N] = alpha * A[M,K] @ B[K,N]   (row-major, all dims %64/%16 == 0)
// 64x64 tile, K-step 16, 256 threads, 4x4 register micro-tile.
// ---------------------------------------------------------------------------
#define GM 64
#define GN 64
#define GK 16

__global__ __launch_bounds__(256)
void sgemm_kernel(const float* __restrict__ A, const float* __restrict__ B,
                  float* __restrict__ C, int M, int N, int K, float alpha) {
    __shared__ float As[GK][GM + 4];
    __shared__ float Bs[GK][GN + 4];

    const int t  = threadIdx.x;
    const int tx = t & 15;
    const int ty = t >> 4;
    const int row0 = blockIdx.y * GM;
    const int col0 = blockIdx.x * GN;

    // load mapping
    const int am = t >> 2;          // 0..63 : A tile row
    const int ak = (t & 3) << 2;    // 0,4,8,12 : A tile k (float4)
    const int bk = t >> 4;          // 0..15 : B tile k
    const int bn = (t & 15) << 2;   // 0..60 : B tile col (float4)

    const float* Ap = A + (size_t)(row0 + am) * K + ak;
    const float* Bp = B + (size_t)bk * N + col0 + bn;

    float acc[4][4];
#pragma unroll
    for (int i = 0; i < 4; i++)
#pragma unroll
        for (int j = 0; j < 4; j++) acc[i][j] = 0.0f;

    for (int k0 = 0; k0 < K; k0 += GK) {
        float4 a4 = *(const float4*)(Ap + k0);
        float4 b4 = *(const float4*)(Bp + (size_t)k0 * N);
        __syncthreads();   // protect previous-iter smem readers
        As[ak + 0][am] = a4.x;
        As[ak + 1][am] = a4.y;
        As[ak + 2][am] = a4.z;
        As[ak + 3][am] = a4.w;
        *(float4*)&Bs[bk][bn] = b4;
        __syncthreads();

#pragma unroll
        for (int k = 0; k < GK; k++) {
            float4 av = *(const float4*)&As[k][ty << 2];
            float4 bv = *(const float4*)&Bs[k][tx << 2];
            acc[0][0] = fmaf(av.x, bv.x, acc[0][0]);
            acc[0][1] = fmaf(av.x, bv.y, acc[0][1]);
            acc[0][2] = fmaf(av.x, bv.z, acc[0][2]);
            acc[0][3] = fmaf(av.x, bv.w, acc[0][3]);
            acc[1][0] = fmaf(av.y, bv.x, acc[1][0]);
            acc[1][1] = fmaf(av.y, bv.y, acc[1][1]);
            acc[1][2] = fmaf(av.y, bv.z, acc[1][2]);
            acc[1][3] = fmaf(av.y, bv.w, acc[1][3]);
            acc[2][0] = fmaf(av.z, bv.x, acc[2][0]);
            acc[2][1] = fmaf(av.z, bv.y, acc[2][1]);
            acc[2][2] = fmaf(av.z, bv.z, acc[2][2]);
            acc[2][3] = fmaf(av.z, bv.w, acc[2][3]);
            acc[3][0] = fmaf(av.w, bv.x, acc[3][0]);
            acc[3][1] = fmaf(av.w, bv.y, acc[3][1]);
            acc[3][2] = fmaf(av.w, bv.z, acc[3][2]);
            acc[3][3] = fmaf(av.w, bv.w, acc[3][3]);
        }
    }

#pragma unroll
    for (int i = 0; i < 4; i++) {
        float4 o;
        o.x = acc[i][0] * alpha;
        o.y = acc[i][1] * alpha;
        o.z = acc[i][2] * alpha;
        o.w = acc[i][3] * alpha;
        *(float4*)(C + (size_t)(row0 + ty * 4 + i) * N + col0 + tx * 4) = o;
    }
}

// ---------------------------------------------------------------------------
// Interleaved RoPE on first 32 dims of each 64-dim head, applied to q and k.
// One thread per (tensor, b, s, h, pair). angle = s * 10000^(-pairIdx/16)
// out[2i]   = x[2i]*cos - x[2i+1]*sin
// out[2i+1] = x[2i+1]*cos + x[2i]*sin
// ---------------------------------------------------------------------------
__global__ void rotary_kernel(float* __restrict__ q, float* __restrict__ k) {
    const int total = BV * SV * HV * 16;  // pairs per tensor
    int idx = blockIdx.x * blockDim.x + threadIdx.x;
    float* base = q;
    if (idx >= total) {
        idx -= total;
        base = k;
        if (idx >= total) return;
    }
    int i = idx & 15;            // pair index 0..15
    int r = idx >> 4;
    int h = r % HV; r /= HV;
    int s = r % SV;
    int b = r / SV;

    float inv = powf(10000.0f, -(float)i / 16.0f);
    float ang = (float)s * inv;
    float sn, cs;
    sincosf(ang, &sn, &cs);

    float* p = base + ((size_t)b * SV + s) * DV + h * KD + 2 * i;
    float x1 = p[0], x2 = p[1];
    p[0] = x1 * cs - x2 * sn;
    p[1] = x2 * cs + x1 * sn;
}

// ---------------------------------------------------------------------------
// Causal flash attention, fp32.
// grid = (S/128, B*H), block = 128 threads, 1 thread per query row.
// q[64] + acc[64] in registers; K/V tiles of 16 rows in SMEM; score reads are
// warp-uniform broadcasts (LDS.128, conflict-free). Online softmax (__expf).
// q already carries the 1/sqrt(64) scale from the projection GEMM.
// ---------------------------------------------------------------------------
#define FA_M 128
#define FA_N 16

__global__ __launch_bounds__(FA_M)
void flash_kernel(const float* __restrict__ Q, const float* __restrict__ K,
                  const float* __restrict__ V, float* __restrict__ Y) {
    const int bh = blockIdx.y;
    const int b = bh / HV;
    const int h = bh % HV;
    const int t = threadIdx.x;
    const int qi = blockIdx.x * FA_M + t;   // global query index

    __shared__ float Ks[FA_N][KD];
    __shared__ float Vs[FA_N][KD];

    // q row -> registers (16 x float4)
    float4 qr[16];
    const float* qp = Q + ((size_t)b * SV + qi) * DV + h * KD;
#pragma unroll
    for (int i = 0; i < 16; i++) qr[i] = *(const float4*)(qp + 4 * i);

    float4 acc[16];
#pragma unroll
    for (int i = 0; i < 16; i++) acc[i] = make_float4(0.f, 0.f, 0.f, 0.f);
    float m = -3.0e38f;
    float l = 0.0f;

    const int kend = (blockIdx.x + 1) * FA_M;  // keys needed by this block
    const int row = t >> 3;        // 16 rows, 8 threads per row
    const int c   = (t & 7) * 8;   // 8 floats per thread

    for (int j0 = 0; j0 < kend; j0 += FA_N) {
        // prefetch next K/V tile into registers before barrier
        const float* kp = K + ((size_t)b * SV + j0 + row) * DV + h * KD + c;
        const float* vp = V + ((size_t)b * SV + j0 + row) * DV + h * KD + c;
        float4 kl0 = *(const float4*)kp;
        float4 kl1 = *(const float4*)(kp + 4);
        float4 vl0 = *(const float4*)vp;
        float4 vl1 = *(const float4*)(vp + 4);
        __syncthreads();
        *(float4*)&Ks[row][c]     = kl0;
        *(float4*)&Ks[row][c + 4] = kl1;
        *(float4*)&Vs[row][c]     = vl0;
        *(float4*)&Vs[row][c + 4] = vl1;
        __syncthreads();

        // scores for this key tile
        float s[FA_N];
#pragma unroll
        for (int j = 0; j < FA_N; j++) {
            float d0 = 0.f, d1 = 0.f, d2 = 0.f, d3 = 0.f;
#pragma unroll
            for (int i = 0; i < 16; i++) {
                float4 kv = *(const float4*)&Ks[j][4 * i];  // broadcast
                d0 = fmaf(qr[i].x, kv.x, d0);
                d1 = fmaf(qr[i].y, kv.y, d1);
                d2 = fmaf(qr[i].z, kv.z, d2);
                d3 = fmaf(qr[i].w, kv.w, d3);
            }
            float sj = (d0 + d1) + (d2 + d3);
            s[j] = (j0 + j <= qi) ? sj : -1e30f;  // causal mask (matches ref)
        }

        // online softmax update
        float mt = m;
#pragma unroll
        for (int j = 0; j < FA_N; j++) mt = fmaxf(mt, s[j]);
        float scale = __expf(m - mt);
        l *= scale;
#pragma unroll
        for (int i = 0; i < 16; i++) {
            acc[i].x *= scale; acc[i].y *= scale;
            acc[i].z *= scale; acc[i].w *= scale;
        }
#pragma unroll
        for (int j = 0; j < FA_N; j++) {
            float p = __expf(s[j] - mt);
            l += p;
#pragma unroll
            for (int i = 0; i < 16; i++) {
                float4 vv = *(const float4*)&Vs[j][4 * i];  // broadcast
                acc[i].x = fmaf(p, vv.x, acc[i].x);
                acc[i].y = fmaf(p, vv.y, acc[i].y);
                acc[i].z = fmaf(p, vv.z, acc[i].z);
                acc[i].w = fmaf(p, vv.w, acc[i].w);
            }
        }
        m = mt;
    }

    float inv = 1.0f / l;
    float* yp = Y + ((size_t)b * SV + qi) * DV + h * KD;
#pragma unroll
    for (int i = 0; i < 16; i++) {
        float4 o = acc[i];
        o.x *= inv; o.y *= inv; o.z *= inv; o.w *= inv;
        *(float4*)(yp + 4 * i) = o;
    }
}

// ---------------------------------------------------------------------------
// kernel_launch: q/k/v projections -> rope -> flash attention -> out proj
// ---------------------------------------------------------------------------
extern "C" void kernel_launch(void* const* d_in, const int* in_sizes, int n_in,
                              void* d_out, int out_size) {
    (void)in_sizes; (void)n_in; (void)out_size;
    const float* x  = (const float*)d_in[0];
    // d_in[1] = mask (causal, known statically) — unused
    const float* Wq = (const float*)d_in[2];
    const float* Wk = (const float*)d_in[3];
    const float* Wv = (const float*)d_in[4];
    const float* Wo = (const float*)d_in[5];
    float* out = (float*)d_out;

    float *q, *k, *v, *y;
    cudaGetSymbolAddress((void**)&q, g_q);
    cudaGetSymbolAddress((void**)&k, g_k);
    cudaGetSymbolAddress((void**)&v, g_v);
    cudaGetSymbolAddress((void**)&y, g_y);

    dim3 ggrid(DV / GN, MROWS / GM);   // (16, 64)
    const float qscale = 0.125f;       // 1/sqrt(64)

    sgemm_kernel<<<ggrid, 256>>>(x, Wq, q, MROWS, DV, DV, qscale);
    sgemm_kernel<<<ggrid, 256>>>(x, Wk, k, MROWS, DV, DV, 1.0f);
    sgemm_kernel<<<ggrid, 256>>>(x, Wv, v, MROWS, DV, DV, 1.0f);

    int pairs2 = 2 * BV * SV * HV * 16;
    rotary_kernel<<<(pairs2 + 255) / 256, 256>>>(q, k);

    dim3 fgrid(SV / FA_M, BV * HV);    // (16, 32)
    flash_kernel<<<fgrid, FA_M>>>(q, k, v, y);

    sgemm_kernel<<<ggrid, 256>>>(y, Wo, out, MROWS, DV, DV, 1.0f);
}

// round 3
// speedup vs baseline: 1.5148x; 1.5148x over previous
#include <cuda_runtime.h>
#include <cuda_bf16.h>
#include <math.h>
#include <stdint.h>

// ---------------------------------------------------------------------------
// Problem constants: B=2, S=2048, D=1024, H=16, head_dim=64, rope dims=32
// ---------------------------------------------------------------------------
#define BV 2
#define HV 16
#define SV 2048
#define DV 1024
#define KD 64
#define MROWS (BV*SV)  // 4096

// Scratch (device globals: allocation-free rule)
__device__ float g_q[MROWS * DV];
__device__ float g_k[MROWS * DV];
__device__ float g_v[MROWS * DV];
__device__ float g_y[MROWS * DV];
__device__ __nv_bfloat16 g_xh[MROWS * DV];
__device__ __nv_bfloat16 g_xl[MROWS * DV];
__device__ __nv_bfloat16 g_yh[MROWS * DV];
__device__ __nv_bfloat16 g_yl[MROWS * DV];
__device__ __nv_bfloat16 g_wh[4 * DV * DV];   // transposed weights [N,K], hi
__device__ __nv_bfloat16 g_wl[4 * DV * DV];   // transposed weights [N,K], lo

// ---------------------------------------------------------------------------
// helpers
// ---------------------------------------------------------------------------
__device__ __forceinline__ uint32_t smem_u32(const void* p) {
    uint32_t a;
    asm("{ .reg .u64 t; cvta.to.shared.u64 t, %1; cvt.u32.u64 %0, t; }"
        : "=r"(a) : "l"(p));
    return a;
}

#define SWZ(o) ((o) ^ (((o) >> 3) & 0x70))

__device__ __forceinline__ void ldm4(uint32_t* r, uint32_t addr) {
    asm volatile("ldmatrix.sync.aligned.m8n8.x4.shared.b16 {%0,%1,%2,%3}, [%4];"
                 : "=r"(r[0]), "=r"(r[1]), "=r"(r[2]), "=r"(r[3]) : "r"(addr));
}

__device__ __forceinline__ void mma_bf16(float* c, const uint32_t* a,
                                         uint32_t b0, uint32_t b1) {
    asm volatile(
        "mma.sync.aligned.m16n8k16.row.col.f32.bf16.bf16.f32 "
        "{%0,%1,%2,%3},{%4,%5,%6,%7},{%8,%9},{%0,%1,%2,%3};"
        : "+f"(c[0]), "+f"(c[1]), "+f"(c[2]), "+f"(c[3])
        : "r"(a[0]), "r"(a[1]), "r"(a[2]), "r"(a[3]), "r"(b0), "r"(b1));
}

__device__ __forceinline__ void cp16(uint32_t saddr, const void* gaddr) {
    asm volatile("cp.async.cg.shared.global [%0], [%1], 16;"
                 :: "r"(saddr), "l"(gaddr) : "memory");
}
#define CP_COMMIT() asm volatile("cp.async.commit_group;" ::: "memory")
#define CP_WAIT1()  asm volatile("cp.async.wait_group 1;" ::: "memory")
#define CP_WAIT0()  asm volatile("cp.async.wait_group 0;" ::: "memory")

// ---------------------------------------------------------------------------
// Elementwise hi/lo bf16 split: hi = bf16(x), lo = bf16(x - hi)
// ---------------------------------------------------------------------------
__global__ void split_kernel(const float* __restrict__ src,
                             __nv_bfloat16* __restrict__ hi,
                             __nv_bfloat16* __restrict__ lo, int n4) {
    int i = blockIdx.x * blockDim.x + threadIdx.x;
    if (i >= n4) return;
    float4 v = ((const float4*)src)[i];
    __nv_bfloat162 hh0 = __floats2bfloat162_rn(v.x, v.y);
    __nv_bfloat162 hh1 = __floats2bfloat162_rn(v.z, v.w);
    __nv_bfloat162 ll0 = __floats2bfloat162_rn(v.x - __low2float(hh0),
                                               v.y - __high2float(hh0));
    __nv_bfloat162 ll1 = __floats2bfloat162_rn(v.z - __low2float(hh1),
                                               v.w - __high2float(hh1));
    *(__nv_bfloat162*)(hi + 4 * i)     = hh0;
    *(__nv_bfloat162*)(hi + 4 * i + 2) = hh1;
    *(__nv_bfloat162*)(lo + 4 * i)     = ll0;
    *(__nv_bfloat162*)(lo + 4 * i + 2) = ll1;
}

// ---------------------------------------------------------------------------
// Weight transpose + split: WT_hi/lo[n*DV + k] <- split(W[k*DV + n])
// ---------------------------------------------------------------------------
__global__ void trans_split_kernel(const float* __restrict__ W,
                                   __nv_bfloat16* __restrict__ hi,
                                   __nv_bfloat16* __restrict__ lo) {
    __shared__ float tile[32][33];
    int bx = blockIdx.x * 32, by = blockIdx.y * 32;
    int tx = threadIdx.x, ty = threadIdx.y;
#pragma unroll
    for (int r = 0; r < 32; r += 8)
        tile[ty + r][tx] = W[(size_t)(by + ty + r) * DV + bx + tx];
    __syncthreads();
#pragma unroll
    for (int r = 0; r < 32; r += 8) {
        float v = tile[tx][ty + r];
        __nv_bfloat16 h = __float2bfloat16_rn(v);
        size_t o = (size_t)(bx + ty + r) * DV + by + tx;
        hi[o] = h;
        lo[o] = __float2bfloat16_rn(v - __bfloat162float(h));
    }
}

// ---------------------------------------------------------------------------
// bf16x3 emulated-fp32 GEMM via mma.sync:
//   C[M,N] = alpha * A[M,K] @ BT[N,K]^T,  A/B pre-split into hi/lo bf16.
// 128x128 block tile, BK=64 (128B SW128 rows), cp.async 2-stage pipeline,
// 8 warps (4m x 2n), warp tile 32x64, m16n8k16.
// ---------------------------------------------------------------------------
#define GBM 128
#define GBN 128
#define GBK 64
#define TILE_BYTES (GBM * GBK * 2)        // 16384 per tile
#define STAGE_BYTES (4 * TILE_BYTES)      // Ah, Al, Bh, Bl
#define GEMM_SMEM (2 * STAGE_BYTES)       // 131072
#define NITER (DV / GBK)                  // 16

__global__ __launch_bounds__(256, 1)
void mma_gemm(const __nv_bfloat16* __restrict__ Ah,
              const __nv_bfloat16* __restrict__ Al,
              const __nv_bfloat16* __restrict__ Bh,
              const __nv_bfloat16* __restrict__ Bl,
              float* __restrict__ C, float alpha) {
    extern __shared__ __align__(1024) char sm[];
    const uint32_t sb = smem_u32(sm);
    const int t = threadIdx.x;
    const int lane = t & 31, wid = t >> 5;
    const int warpM = wid & 3, warpN = wid >> 2;
    const int row0 = blockIdx.y * GBM;
    const int col0 = blockIdx.x * GBN;

    const __nv_bfloat16* srcs[4] = {
        Ah + (size_t)row0 * DV, Al + (size_t)row0 * DV,
        Bh + (size_t)col0 * DV, Bl + (size_t)col0 * DV };

    // copy mapping: chunk id = t + 256*j -> row m = id>>3, 16B chunk c = id&7
    const int cm = t >> 3;
    const int cc = t & 7;

    float acc[2][8][4];
#pragma unroll
    for (int i = 0; i < 2; i++)
#pragma unroll
        for (int j = 0; j < 8; j++)
#pragma unroll
            for (int r = 0; r < 4; r++) acc[i][j][r] = 0.0f;

    // ldmatrix per-lane address components
    const int sub = lane >> 3, l7 = lane & 7;
    const int rowA0 = warpM * 32 + ((sub & 1) << 3) + l7;        // mt=0
    const int rowA1 = rowA0 + 16;                                 // mt=1
    const int kA = (sub >> 1);                                    // +8k half
    int rowB[4];
#pragma unroll
    for (int p = 0; p < 4; p++)
        rowB[p] = warpN * 64 + p * 16 + ((sub >> 1) << 3) + l7;
    const int kB = (sub & 1);

    // prologue: stage 0
    {
        const int k0 = 0;
#pragma unroll
        for (int tile = 0; tile < 4; tile++) {
#pragma unroll
            for (int j = 0; j < 4; j++) {
                int m = cm + 32 * j;
                const __nv_bfloat16* g = srcs[tile] + (size_t)m * DV + k0 + cc * 8;
                uint32_t sa = sb + tile * TILE_BYTES + SWZ(m * 128 + cc * 16);
                cp16(sa, g);
            }
        }
        CP_COMMIT();
    }

    for (int it = 0; it < NITER; it++) {
        const int buf = it & 1;
        __syncthreads();   // all warps done with mma on buffer being refilled
        if (it + 1 < NITER) {
            const int k0 = (it + 1) * GBK;
            const uint32_t stb = sb + ((it + 1) & 1) * STAGE_BYTES;
#pragma unroll
            for (int tile = 0; tile < 4; tile++) {
#pragma unroll
                for (int j = 0; j < 4; j++) {
                    int m = cm + 32 * j;
                    const __nv_bfloat16* g = srcs[tile] + (size_t)m * DV + k0 + cc * 8;
                    uint32_t sa = stb + tile * TILE_BYTES + SWZ(m * 128 + cc * 16);
                    cp16(sa, g);
                }
            }
            CP_COMMIT();
            CP_WAIT1();
        } else {
            CP_WAIT0();
        }
        __syncthreads();   // stage `it` visible to all

        const uint32_t ahB = sb + buf * STAGE_BYTES;
        const uint32_t alB = ahB + TILE_BYTES;
        const uint32_t bhB = ahB + 2 * TILE_BYTES;
        const uint32_t blB = ahB + 3 * TILE_BYTES;

#pragma unroll
        for (int ks = 0; ks < 4; ks++) {
            const int kcA = ks * 2 + kA;
            const int kcB = ks * 2 + kB;
            uint32_t ah[2][4], al[2][4];
            ldm4(ah[0], ahB + SWZ(rowA0 * 128 + kcA * 16));
            ldm4(ah[1], ahB + SWZ(rowA1 * 128 + kcA * 16));
            ldm4(al[0], alB + SWZ(rowA0 * 128 + kcA * 16));
            ldm4(al[1], alB + SWZ(rowA1 * 128 + kcA * 16));
            uint32_t bh[4][4], bl[4][4];
#pragma unroll
            for (int p = 0; p < 4; p++) {
                ldm4(bh[p], bhB + SWZ(rowB[p] * 128 + kcB * 16));
                ldm4(bl[p], blB + SWZ(rowB[p] * 128 + kcB * 16));
            }
#pragma unroll
            for (int mt = 0; mt < 2; mt++) {
#pragma unroll
                for (int nt = 0; nt < 8; nt++) {
                    const int p = nt >> 1, o = (nt & 1) * 2;
                    mma_bf16(acc[mt][nt], ah[mt], bh[p][o], bh[p][o + 1]);
                    mma_bf16(acc[mt][nt], ah[mt], bl[p][o], bl[p][o + 1]);
                    mma_bf16(acc[mt][nt], al[mt], bh[p][o], bh[p][o + 1]);
                }
            }
        }
    }

    // epilogue
#pragma unroll
    for (int mt = 0; mt < 2; mt++) {
#pragma unroll
        for (int nt = 0; nt < 8; nt++) {
            int r = row0 + warpM * 32 + mt * 16 + (lane >> 2);
            int c = col0 + warpN * 64 + nt * 8 + (lane & 3) * 2;
            float2 v0 = make_float2(acc[mt][nt][0] * alpha, acc[mt][nt][1] * alpha);
            float2 v1 = make_float2(acc[mt][nt][2] * alpha, acc[mt][nt][3] * alpha);
            *(float2*)(C + (size_t)r * DV + c) = v0;
            *(float2*)(C + (size_t)(r + 8) * DV + c) = v1;
        }
    }
}

// ---------------------------------------------------------------------------
// Interleaved RoPE on first 32 dims of each 64-dim head (q and k).
// ---------------------------------------------------------------------------
__global__ void rotary_kernel(float* __restrict__ q, float* __restrict__ k) {
    const int total = BV * SV * HV * 16;
    int idx = blockIdx.x * blockDim.x + threadIdx.x;
    float* base = q;
    if (idx >= total) {
        idx -= total;
        base = k;
        if (idx >= total) return;
    }
    int i = idx & 15;
    int r = idx >> 4;
    int h = r % HV; r /= HV;
    int s = r % SV;
    int b = r / SV;

    float inv = powf(10000.0f, -(float)i / 16.0f);
    float ang = (float)s * inv;
    float sn, cs;
    sincosf(ang, &sn, &cs);

    float* p = base + ((size_t)b * SV + s) * DV + h * KD + 2 * i;
    float x1 = p[0], x2 = p[1];
    p[0] = x1 * cs - x2 * sn;
    p[1] = x2 * cs + x1 * sn;
}

// ---------------------------------------------------------------------------
// Causal flash attention, fp32 (unchanged from passing round-1 kernel).
// ---------------------------------------------------------------------------
#define FA_M 128
#define FA_N 16

__global__ __launch_bounds__(FA_M)
void flash_kernel(const float* __restrict__ Q, const float* __restrict__ K,
                  const float* __restrict__ V, float* __restrict__ Y) {
    const int bh = blockIdx.y;
    const int b = bh / HV;
    const int h = bh % HV;
    const int t = threadIdx.x;
    const int qi = blockIdx.x * FA_M + t;

    __shared__ float Ks[FA_N][KD];
    __shared__ float Vs[FA_N][KD];

    float4 qr[16];
    const float* qp = Q + ((size_t)b * SV + qi) * DV + h * KD;
#pragma unroll
    for (int i = 0; i < 16; i++) qr[i] = *(const float4*)(qp + 4 * i);

    float4 acc[16];
#pragma unroll
    for (int i = 0; i < 16; i++) acc[i] = make_float4(0.f, 0.f, 0.f, 0.f);
    float m = -3.0e38f;
    float l = 0.0f;

    const int kend = (blockIdx.x + 1) * FA_M;
    const int row = t >> 3;
    const int c   = (t & 7) * 8;

    for (int j0 = 0; j0 < kend; j0 += FA_N) {
        const float* kp = K + ((size_t)b * SV + j0 + row) * DV + h * KD + c;
        const float* vp = V + ((size_t)b * SV + j0 + row) * DV + h * KD + c;
        float4 kl0 = *(const float4*)kp;
        float4 kl1 = *(const float4*)(kp + 4);
        float4 vl0 = *(const float4*)vp;
        float4 vl1 = *(const float4*)(vp + 4);
        __syncthreads();
        *(float4*)&Ks[row][c]     = kl0;
        *(float4*)&Ks[row][c + 4] = kl1;
        *(float4*)&Vs[row][c]     = vl0;
        *(float4*)&Vs[row][c + 4] = vl1;
        __syncthreads();

        float s[FA_N];
#pragma unroll
        for (int j = 0; j < FA_N; j++) {
            float d0 = 0.f, d1 = 0.f, d2 = 0.f, d3 = 0.f;
#pragma unroll
            for (int i = 0; i < 16; i++) {
                float4 kv = *(const float4*)&Ks[j][4 * i];
                d0 = fmaf(qr[i].x, kv.x, d0);
                d1 = fmaf(qr[i].y, kv.y, d1);
                d2 = fmaf(qr[i].z, kv.z, d2);
                d3 = fmaf(qr[i].w, kv.w, d3);
            }
            float sj = (d0 + d1) + (d2 + d3);
            s[j] = (j0 + j <= qi) ? sj : -1e30f;
        }

        float mt = m;
#pragma unroll
        for (int j = 0; j < FA_N; j++) mt = fmaxf(mt, s[j]);
        float scale = __expf(m - mt);
        l *= scale;
#pragma unroll
        for (int i = 0; i < 16; i++) {
            acc[i].x *= scale; acc[i].y *= scale;
            acc[i].z *= scale; acc[i].w *= scale;
        }
#pragma unroll
        for (int j = 0; j < FA_N; j++) {
            float p = __expf(s[j] - mt);
            l += p;
#pragma unroll
            for (int i = 0; i < 16; i++) {
                float4 vv = *(const float4*)&Vs[j][4 * i];
                acc[i].x = fmaf(p, vv.x, acc[i].x);
                acc[i].y = fmaf(p, vv.y, acc[i].y);
                acc[i].z = fmaf(p, vv.z, acc[i].z);
                acc[i].w = fmaf(p, vv.w, acc[i].w);
            }
        }
        m = mt;
    }

    float inv = 1.0f / l;
    float* yp = Y + ((size_t)b * SV + qi) * DV + h * KD;
#pragma unroll
    for (int i = 0; i < 16; i++) {
        float4 o = acc[i];
        o.x *= inv; o.y *= inv; o.z *= inv; o.w *= inv;
        *(float4*)(yp + 4 * i) = o;
    }
}

// ---------------------------------------------------------------------------
// kernel_launch
// ---------------------------------------------------------------------------
extern "C" void kernel_launch(void* const* d_in, const int* in_sizes, int n_in,
                              void* d_out, int out_size) {
    (void)in_sizes; (void)n_in; (void)out_size;
    const float* x  = (const float*)d_in[0];
    const float* Wq = (const float*)d_in[2];
    const float* Wk = (const float*)d_in[3];
    const float* Wv = (const float*)d_in[4];
    const float* Wo = (const float*)d_in[5];
    float* out = (float*)d_out;

    float *q, *k, *v, *y;
    __nv_bfloat16 *xh, *xl, *yh, *yl, *wh, *wl;
    cudaGetSymbolAddress((void**)&q, g_q);
    cudaGetSymbolAddress((void**)&k, g_k);
    cudaGetSymbolAddress((void**)&v, g_v);
    cudaGetSymbolAddress((void**)&y, g_y);
    cudaGetSymbolAddress((void**)&xh, g_xh);
    cudaGetSymbolAddress((void**)&xl, g_xl);
    cudaGetSymbolAddress((void**)&yh, g_yh);
    cudaGetSymbolAddress((void**)&yl, g_yl);
    cudaGetSymbolAddress((void**)&wh, g_wh);
    cudaGetSymbolAddress((void**)&wl, g_wl);

    cudaFuncSetAttribute(mma_gemm, cudaFuncAttributeMaxDynamicSharedMemorySize,
                         GEMM_SMEM);

    // split x into hi/lo bf16
    int n4 = MROWS * DV / 4;
    split_kernel<<<(n4 + 255) / 256, 256>>>(x, xh, xl, n4);

    // transpose + split weights
    dim3 tgrid(DV / 32, DV / 32);
    dim3 tblk(32, 8);
    trans_split_kernel<<<tgrid, tblk>>>(Wq, wh + 0 * DV * DV, wl + 0 * DV * DV);
    trans_split_kernel<<<tgrid, tblk>>>(Wk, wh + 1 * DV * DV, wl + 1 * DV * DV);
    trans_split_kernel<<<tgrid, tblk>>>(Wv, wh + 2 * DV * DV, wl + 2 * DV * DV);
    trans_split_kernel<<<tgrid, tblk>>>(Wo, wh + 3 * DV * DV, wl + 3 * DV * DV);

    dim3 ggrid(DV / GBN, MROWS / GBM);   // (8, 32)
    mma_gemm<<<ggrid, 256, GEMM_SMEM>>>(xh, xl, wh + 0 * DV * DV, wl + 0 * DV * DV, q, 0.125f);
    mma_gemm<<<ggrid, 256, GEMM_SMEM>>>(xh, xl, wh + 1 * DV * DV, wl + 1 * DV * DV, k, 1.0f);
    mma_gemm<<<ggrid, 256, GEMM_SMEM>>>(xh, xl, wh + 2 * DV * DV, wl + 2 * DV * DV, v, 1.0f);

    int pairs2 = 2 * BV * SV * HV * 16;
    rotary_kernel<<<(pairs2 + 255) / 256, 256>>>(q, k);

    dim3 fgrid(SV / FA_M, BV * HV);
    flash_kernel<<<fgrid, FA_M>>>(q, k, v, y);

    split_kernel<<<(n4 + 255) / 256, 256>>>(y, yh, yl, n4);
    mma_gemm<<<ggrid, 256, GEMM_SMEM>>>(yh, yl, wh + 3 * DV * DV, wl + 3 * DV * DV, out, 1.0f);
}

// round 4
// speedup vs baseline: 3.0615x; 2.0211x over previous
#include <cuda_runtime.h>
#include <cuda_bf16.h>
#include <math.h>
#include <stdint.h>
#include <string.h>

// ---------------------------------------------------------------------------
// Problem constants: B=2, S=2048, D=1024, H=16, head_dim=64, rope dims=32
// ---------------------------------------------------------------------------
#define BV 2
#define HV 16
#define SV 2048
#define DV 1024
#define KD 64
#define MROWS (BV*SV)        // 4096
#define HEADROWS (BV*HV*SV)  // 65536

// Scratch (device globals: allocation-free rule)
__device__ float g_qkv[MROWS * 3 * DV];
__device__ __nv_bfloat16 g_xh[MROWS * DV];
__device__ __nv_bfloat16 g_xl[MROWS * DV];
__device__ __nv_bfloat16 g_wh[4 * DV * DV];
__device__ __nv_bfloat16 g_wl[4 * DV * DV];
__device__ __nv_bfloat16 g_qh[HEADROWS * KD];
__device__ __nv_bfloat16 g_ql[HEADROWS * KD];
__device__ __nv_bfloat16 g_kh[HEADROWS * KD];
__device__ __nv_bfloat16 g_kl[HEADROWS * KD];
__device__ __nv_bfloat16 g_vh[HEADROWS * KD];
__device__ __nv_bfloat16 g_vl[HEADROWS * KD];
__device__ __nv_bfloat16 g_yh[MROWS * DV];
__device__ __nv_bfloat16 g_yl[MROWS * DV];

// ---------------------------------------------------------------------------
// helpers
// ---------------------------------------------------------------------------
__device__ __forceinline__ uint32_t smem_u32(const void* p) {
    uint32_t a;
    asm("{ .reg .u64 t; cvta.to.shared.u64 t, %1; cvt.u32.u64 %0, t; }"
        : "=r"(a) : "l"(p));
    return a;
}

#define SWZ(o) ((o) ^ (((o) >> 3) & 0x70))

__device__ __forceinline__ void ldm4(uint32_t* r, uint32_t addr) {
    asm volatile("ldmatrix.sync.aligned.m8n8.x4.shared.b16 {%0,%1,%2,%3}, [%4];"
                 : "=r"(r[0]), "=r"(r[1]), "=r"(r[2]), "=r"(r[3]) : "r"(addr));
}

__device__ __forceinline__ void ldm4t(uint32_t* r, uint32_t addr) {
    asm volatile("ldmatrix.sync.aligned.m8n8.x4.trans.shared.b16 {%0,%1,%2,%3}, [%4];"
                 : "=r"(r[0]), "=r"(r[1]), "=r"(r[2]), "=r"(r[3]) : "r"(addr));
}

__device__ __forceinline__ void mma_bf16(float* c, const uint32_t* a,
                                         uint32_t b0, uint32_t b1) {
    asm volatile(
        "mma.sync.aligned.m16n8k16.row.col.f32.bf16.bf16.f32 "
        "{%0,%1,%2,%3},{%4,%5,%6,%7},{%8,%9},{%0,%1,%2,%3};"
        : "+f"(c[0]), "+f"(c[1]), "+f"(c[2]), "+f"(c[3])
        : "r"(a[0]), "r"(a[1]), "r"(a[2]), "r"(a[3]), "r"(b0), "r"(b1));
}

__device__ __forceinline__ void cp16(uint32_t saddr, const void* gaddr) {
    asm volatile("cp.async.cg.shared.global [%0], [%1], 16;"
                 :: "r"(saddr), "l"(gaddr) : "memory");
}
#define CP_COMMIT() asm volatile("cp.async.commit_group;" ::: "memory")
#define CP_WAIT1()  asm volatile("cp.async.wait_group 1;" ::: "memory")
#define CP_WAIT0()  asm volatile("cp.async.wait_group 0;" ::: "memory")

__device__ __forceinline__ uint32_t b2u(__nv_bfloat162 v) {
    uint32_t u;
    memcpy(&u, &v, 4);
    return u;
}

// ---------------------------------------------------------------------------
// Elementwise hi/lo bf16 split of x
// ---------------------------------------------------------------------------
__global__ void split_kernel(const float* __restrict__ src,
                             __nv_bfloat16* __restrict__ hi,
                             __nv_bfloat16* __restrict__ lo, int n4) {
    int i = blockIdx.x * blockDim.x + threadIdx.x;
    if (i >= n4) return;
    float4 v = ((const float4*)src)[i];
    __nv_bfloat162 hh0 = __floats2bfloat162_rn(v.x, v.y);
    __nv_bfloat162 hh1 = __floats2bfloat162_rn(v.z, v.w);
    __nv_bfloat162 ll0 = __floats2bfloat162_rn(v.x - __low2float(hh0),
                                               v.y - __high2float(hh0));
    __nv_bfloat162 ll1 = __floats2bfloat162_rn(v.z - __low2float(hh1),
                                               v.w - __high2float(hh1));
    *(__nv_bfloat162*)(hi + 4 * i)     = hh0;
    *(__nv_bfloat162*)(hi + 4 * i + 2) = hh1;
    *(__nv_bfloat162*)(lo + 4 * i)     = ll0;
    *(__nv_bfloat162*)(lo + 4 * i + 2) = ll1;
}

// ---------------------------------------------------------------------------
// Weight transpose + scale + split: WT_hi/lo[n*DV + k] <- split(s*W[k*DV + n])
// ---------------------------------------------------------------------------
__global__ void trans_split_kernel(const float* __restrict__ W,
                                   __nv_bfloat16* __restrict__ hi,
                                   __nv_bfloat16* __restrict__ lo, float scale) {
    __shared__ float tile[32][33];
    int bx = blockIdx.x * 32, by = blockIdx.y * 32;
    int tx = threadIdx.x, ty = threadIdx.y;
#pragma unroll
    for (int r = 0; r < 32; r += 8)
        tile[ty + r][tx] = W[(size_t)(by + ty + r) * DV + bx + tx];
    __syncthreads();
#pragma unroll
    for (int r = 0; r < 32; r += 8) {
        float v = tile[tx][ty + r] * scale;
        __nv_bfloat16 h = __float2bfloat16_rn(v);
        size_t o = (size_t)(bx + ty + r) * DV + by + tx;
        hi[o] = h;
        lo[o] = __float2bfloat16_rn(v - __bfloat162float(h));
    }
}

// ---------------------------------------------------------------------------
// bf16x3 emulated-fp32 GEMM: C[M x N] = A[M x K=DV] @ BT[N x K]^T, ldc param.
// 128x128 block tile, BK=64, cp.async double buffer, 8 warps.
// ---------------------------------------------------------------------------
#define GBM 128
#define GBN 128
#define GBK 64
#define TILE_BYTES (GBM * GBK * 2)
#define STAGE_BYTES (4 * TILE_BYTES)
#define GEMM_SMEM (2 * STAGE_BYTES)
#define NITER (DV / GBK)

__global__ __launch_bounds__(256, 1)
void mma_gemm(const __nv_bfloat16* __restrict__ Ah,
              const __nv_bfloat16* __restrict__ Al,
              const __nv_bfloat16* __restrict__ Bh,
              const __nv_bfloat16* __restrict__ Bl,
              float* __restrict__ C, int ldc) {
    extern __shared__ __align__(1024) char sm[];
    const uint32_t sb = smem_u32(sm);
    const int t = threadIdx.x;
    const int lane = t & 31, wid = t >> 5;
    const int warpM = wid & 3, warpN = wid >> 2;
    const int row0 = blockIdx.y * GBM;
    const int col0 = blockIdx.x * GBN;

    const __nv_bfloat16* srcs[4] = {
        Ah + (size_t)row0 * DV, Al + (size_t)row0 * DV,
        Bh + (size_t)col0 * DV, Bl + (size_t)col0 * DV };

    const int cm = t >> 3;
    const int cc = t & 7;

    float acc[2][8][4];
#pragma unroll
    for (int i = 0; i < 2; i++)
#pragma unroll
        for (int j = 0; j < 8; j++)
#pragma unroll
            for (int r = 0; r < 4; r++) acc[i][j][r] = 0.0f;

    const int sub = lane >> 3, l7 = lane & 7;
    const int rowA0 = warpM * 32 + ((sub & 1) << 3) + l7;
    const int rowA1 = rowA0 + 16;
    const int kA = (sub >> 1);
    int rowB[4];
#pragma unroll
    for (int p = 0; p < 4; p++)
        rowB[p] = warpN * 64 + p * 16 + ((sub >> 1) << 3) + l7;
    const int kB = (sub & 1);

    {
#pragma unroll
        for (int tile = 0; tile < 4; tile++) {
#pragma unroll
            for (int j = 0; j < 4; j++) {
                int m = cm + 32 * j;
                cp16(sb + tile * TILE_BYTES + SWZ(m * 128 + cc * 16),
                     srcs[tile] + (size_t)m * DV + cc * 8);
            }
        }
        CP_COMMIT();
    }

    for (int it = 0; it < NITER; it++) {
        const int buf = it & 1;
        __syncthreads();
        if (it + 1 < NITER) {
            const int k0 = (it + 1) * GBK;
            const uint32_t stb = sb + ((it + 1) & 1) * STAGE_BYTES;
#pragma unroll
            for (int tile = 0; tile < 4; tile++) {
#pragma unroll
                for (int j = 0; j < 4; j++) {
                    int m = cm + 32 * j;
                    cp16(stb + tile * TILE_BYTES + SWZ(m * 128 + cc * 16),
                         srcs[tile] + (size_t)m * DV + k0 + cc * 8);
                }
            }
            CP_COMMIT();
            CP_WAIT1();
        } else {
            CP_WAIT0();
        }
        __syncthreads();

        const uint32_t ahB = sb + buf * STAGE_BYTES;
        const uint32_t alB = ahB + TILE_BYTES;
        const uint32_t bhB = ahB + 2 * TILE_BYTES;
        const uint32_t blB = ahB + 3 * TILE_BYTES;

#pragma unroll
        for (int ks = 0; ks < 4; ks++) {
            const int kcA = ks * 2 + kA;
            const int kcB = ks * 2 + kB;
            uint32_t ah[2][4], al[2][4];
            ldm4(ah[0], ahB + SWZ(rowA0 * 128 + kcA * 16));
            ldm4(ah[1], ahB + SWZ(rowA1 * 128 + kcA * 16));
            ldm4(al[0], alB + SWZ(rowA0 * 128 + kcA * 16));
            ldm4(al[1], alB + SWZ(rowA1 * 128 + kcA * 16));
            uint32_t bh[4][4], bl[4][4];
#pragma unroll
            for (int p = 0; p < 4; p++) {
                ldm4(bh[p], bhB + SWZ(rowB[p] * 128 + kcB * 16));
                ldm4(bl[p], blB + SWZ(rowB[p] * 128 + kcB * 16));
            }
#pragma unroll
            for (int mt = 0; mt < 2; mt++) {
#pragma unroll
                for (int nt = 0; nt < 8; nt++) {
                    const int p = nt >> 1, o = (nt & 1) * 2;
                    mma_bf16(acc[mt][nt], ah[mt], bh[p][o], bh[p][o + 1]);
                    mma_bf16(acc[mt][nt], ah[mt], bl[p][o], bl[p][o + 1]);
                    mma_bf16(acc[mt][nt], al[mt], bh[p][o], bh[p][o + 1]);
                }
            }
        }
    }

#pragma unroll
    for (int mt = 0; mt < 2; mt++) {
#pragma unroll
        for (int nt = 0; nt < 8; nt++) {
            int r = row0 + warpM * 32 + mt * 16 + (lane >> 2);
            int c = col0 + warpN * 64 + nt * 8 + (lane & 3) * 2;
            *(float2*)(C + (size_t)r * ldc + c) =
                make_float2(acc[mt][nt][0], acc[mt][nt][1]);
            *(float2*)(C + (size_t)(r + 8) * ldc + c) =
                make_float2(acc[mt][nt][2], acc[mt][nt][3]);
        }
    }
}

// ---------------------------------------------------------------------------
// RoPE + hi/lo split + repack to head-major [B,H,S,64].
// 16 threads per (tensor, b, h, s) row; each thread handles 4 dims.
// ---------------------------------------------------------------------------
__global__ void rope_split_kernel(const float* __restrict__ qkv,
                                  __nv_bfloat16* __restrict__ qh, __nv_bfloat16* __restrict__ ql,
                                  __nv_bfloat16* __restrict__ kh, __nv_bfloat16* __restrict__ kl,
                                  __nv_bfloat16* __restrict__ vh, __nv_bfloat16* __restrict__ vl) {
    int idx = blockIdx.x * blockDim.x + threadIdx.x;
    int lane16 = idx & 15;
    int row = idx >> 4;                 // 0 .. 3*BV*HV*SV-1
    int s = row % SV;
    int r2 = row / SV;
    int bh = r2 % (BV * HV);
    int tt = r2 / (BV * HV);            // 0=q, 1=k, 2=v
    int b = bh / HV, h = bh % HV;

    const float* src = qkv + ((size_t)(b * SV + s)) * (3 * DV) + tt * DV + h * KD + lane16 * 4;
    float4 v = *(const float4*)src;

    if (tt < 2 && lane16 < 8) {
        int i0 = lane16 * 2;
        float inv0 = powf(10000.0f, -(float)i0 / 16.0f);
        float inv1 = powf(10000.0f, -(float)(i0 + 1) / 16.0f);
        float sn0, cs0, sn1, cs1;
        sincosf((float)s * inv0, &sn0, &cs0);
        sincosf((float)s * inv1, &sn1, &cs1);
        float a = v.x * cs0 - v.y * sn0;
        float bq = v.y * cs0 + v.x * sn0;
        float c = v.z * cs1 - v.w * sn1;
        float d = v.w * cs1 + v.z * sn1;
        v = make_float4(a, bq, c, d);
    }

    __nv_bfloat16* dh = (tt == 0) ? qh : (tt == 1) ? kh : vh;
    __nv_bfloat16* dl = (tt == 0) ? ql : (tt == 1) ? kl : vl;
    size_t o = ((size_t)bh * SV + s) * KD + lane16 * 4;

    __nv_bfloat162 h0 = __floats2bfloat162_rn(v.x, v.y);
    __nv_bfloat162 h1 = __floats2bfloat162_rn(v.z, v.w);
    __nv_bfloat162 l0 = __floats2bfloat162_rn(v.x - __low2float(h0), v.y - __high2float(h0));
    __nv_bfloat162 l1 = __floats2bfloat162_rn(v.z - __low2float(h1), v.w - __high2float(h1));
    *(__nv_bfloat162*)(dh + o)     = h0;
    *(__nv_bfloat162*)(dh + o + 2) = h1;
    *(__nv_bfloat162*)(dl + o)     = l0;
    *(__nv_bfloat162*)(dl + o + 2) = l1;
}

// ---------------------------------------------------------------------------
// Tensor-core causal flash attention (bf16x3 QK and PV, fp32 softmax).
// grid = (S/128, B*H), 256 threads (8 warps), warp owns 16 query rows.
// SMEM: Qh,Ql (32KB) + 2-stage {Kh,Kl,Vh,Vl} (2x64KB) = 160KB.
// Writes yh/yl bf16 hi/lo directly in [B,S,D] layout.
// ---------------------------------------------------------------------------
#define FA_SMEM (32768 + 2 * 65536)

__device__ __forceinline__ void fa_load_kv(
    uint32_t base, const __nv_bfloat16* kh, const __nv_bfloat16* kl,
    const __nv_bfloat16* vh, const __nv_bfloat16* vl,
    int kt, int cm, int cc) {
    const __nv_bfloat16* srcs[4] = { kh, kl, vh, vl };
#pragma unroll
    for (int tt = 0; tt < 4; tt++) {
#pragma unroll
        for (int j = 0; j < 4; j++) {
            int r = cm + 32 * j;
            cp16(base + tt * 16384 + SWZ(r * 128 + cc * 16),
                 srcs[tt] + (size_t)(kt * 128 + r) * KD + cc * 8);
        }
    }
    CP_COMMIT();
}

__global__ __launch_bounds__(256, 1)
void flash_mma(const __nv_bfloat16* __restrict__ qh, const __nv_bfloat16* __restrict__ ql,
               const __nv_bfloat16* __restrict__ kh, const __nv_bfloat16* __restrict__ kl,
               const __nv_bfloat16* __restrict__ vh, const __nv_bfloat16* __restrict__ vl,
               __nv_bfloat16* __restrict__ yhp, __nv_bfloat16* __restrict__ ylp) {
    extern __shared__ __align__(1024) char sm[];
    const uint32_t sb = smem_u32(sm);
    const int t = threadIdx.x, lane = t & 31, w = t >> 5;
    const int qt = blockIdx.x, bh = blockIdx.y;
    const size_t ho = (size_t)bh * SV * KD;

    const int cm = t >> 3, cc = t & 7;

    // async-load Q tiles (group 0)
    {
        const __nv_bfloat16* qsrc[2] = { qh + ho + (size_t)qt * 128 * KD,
                                         ql + ho + (size_t)qt * 128 * KD };
#pragma unroll
        for (int tt = 0; tt < 2; tt++) {
#pragma unroll
            for (int j = 0; j < 4; j++) {
                int r = cm + 32 * j;
                cp16(sb + tt * 16384 + SWZ(r * 128 + cc * 16),
                     qsrc[tt] + (size_t)r * KD + cc * 8);
            }
        }
        CP_COMMIT();
    }
    // KV tile 0 (group 1)
    fa_load_kv(sb + 32768, kh + ho, kl + ho, vh + ho, vl + ho, 0, cm, cc);

    const int nt = qt + 1;
    const int sub = lane >> 3, l7 = lane & 7;

    uint32_t qfh[4][4], qfl[4][4];
    float m0 = -3.0e38f, m1 = -3.0e38f, l0 = 0.0f, l1 = 0.0f;
    float yacc[8][4];
#pragma unroll
    for (int p = 0; p < 8; p++)
#pragma unroll
        for (int e = 0; e < 4; e++) yacc[p][e] = 0.0f;

    for (int kt = 0; kt < nt; kt++) {
        const int st = kt & 1;
        CP_WAIT0();
        __syncthreads();

        if (kt == 0) {
            const int rA = w * 16 + ((sub & 1) << 3) + l7;
            const int kA = sub >> 1;
#pragma unroll
            for (int kc = 0; kc < 4; kc++) {
                uint32_t off = SWZ(rA * 128 + (kc * 2 + kA) * 16);
                ldm4(qfh[kc], sb + off);
                ldm4(qfl[kc], sb + 16384 + off);
            }
        }
        // prefetch next KV tile (overlaps compute)
        if (kt + 1 < nt)
            fa_load_kv(sb + 32768 + (st ^ 1) * 65536,
                       kh + ho, kl + ho, vh + ho, vl + ho, kt + 1, cm, cc);

        const uint32_t KhB = sb + 32768 + st * 65536;
        const uint32_t KlB = KhB + 16384;
        const uint32_t VhB = KhB + 32768;
        const uint32_t VlB = KhB + 49152;

        // ---- S = Q K^T (bf16x3) ----
        float sacc[16][4];
#pragma unroll
        for (int n8 = 0; n8 < 16; n8++)
#pragma unroll
            for (int e = 0; e < 4; e++) sacc[n8][e] = 0.0f;

        const int rB = ((sub >> 1) << 3) + l7;
        const int kB = sub & 1;
#pragma unroll
        for (int kc = 0; kc < 4; kc++) {
#pragma unroll
            for (int p = 0; p < 8; p++) {
                uint32_t off = SWZ((p * 16 + rB) * 128 + (kc * 2 + kB) * 16);
                uint32_t kh4[4], kl4[4];
                ldm4(kh4, KhB + off);
                ldm4(kl4, KlB + off);
                mma_bf16(sacc[2 * p], qfh[kc], kh4[0], kh4[1]);
                mma_bf16(sacc[2 * p], qfh[kc], kl4[0], kl4[1]);
                mma_bf16(sacc[2 * p], qfl[kc], kh4[0], kh4[1]);
                mma_bf16(sacc[2 * p + 1], qfh[kc], kh4[2], kh4[3]);
                mma_bf16(sacc[2 * p + 1], qfh[kc], kl4[2], kl4[3]);
                mma_bf16(sacc[2 * p + 1], qfl[kc], kh4[2], kh4[3]);
            }
        }

        // causal mask on diagonal tile
        const int rr0 = w * 16 + (lane >> 2);
        if (kt == qt) {
#pragma unroll
            for (int n8 = 0; n8 < 16; n8++) {
                int cb = n8 * 8 + (lane & 3) * 2;
                if (cb     > rr0)     sacc[n8][0] = -1e30f;
                if (cb + 1 > rr0)     sacc[n8][1] = -1e30f;
                if (cb     > rr0 + 8) sacc[n8][2] = -1e30f;
                if (cb + 1 > rr0 + 8) sacc[n8][3] = -1e30f;
            }
        }

        // ---- online softmax ----
        float mx0 = -3.0e38f, mx1 = -3.0e38f;
#pragma unroll
        for (int n8 = 0; n8 < 16; n8++) {
            mx0 = fmaxf(mx0, fmaxf(sacc[n8][0], sacc[n8][1]));
            mx1 = fmaxf(mx1, fmaxf(sacc[n8][2], sacc[n8][3]));
        }
        mx0 = fmaxf(mx0, __shfl_xor_sync(0xffffffffu, mx0, 1));
        mx0 = fmaxf(mx0, __shfl_xor_sync(0xffffffffu, mx0, 2));
        mx1 = fmaxf(mx1, __shfl_xor_sync(0xffffffffu, mx1, 1));
        mx1 = fmaxf(mx1, __shfl_xor_sync(0xffffffffu, mx1, 2));
        const float mt0 = fmaxf(m0, mx0), mt1 = fmaxf(m1, mx1);
        const float sc0 = __expf(m0 - mt0), sc1 = __expf(m1 - mt1);
        l0 *= sc0; l1 *= sc1;
#pragma unroll
        for (int p = 0; p < 8; p++) {
            yacc[p][0] *= sc0; yacc[p][1] *= sc0;
            yacc[p][2] *= sc1; yacc[p][3] *= sc1;
        }
        m0 = mt0; m1 = mt1;

        // p = exp(s - m), split to hi/lo A-fragments in registers
        uint32_t aH[8][4], aL[8][4];
        float rs0 = 0.0f, rs1 = 0.0f;
#pragma unroll
        for (int kc = 0; kc < 8; kc++) {
#pragma unroll
            for (int e = 0; e < 2; e++) {
                const int n8 = 2 * kc + e;
                float p0 = __expf(sacc[n8][0] - mt0);
                float p1 = __expf(sacc[n8][1] - mt0);
                float p2 = __expf(sacc[n8][2] - mt1);
                float p3 = __expf(sacc[n8][3] - mt1);
                rs0 += p0 + p1; rs1 += p2 + p3;
                __nv_bfloat162 h01 = __floats2bfloat162_rn(p0, p1);
                __nv_bfloat162 h23 = __floats2bfloat162_rn(p2, p3);
                aH[kc][2 * e]     = b2u(h01);
                aH[kc][2 * e + 1] = b2u(h23);
                __nv_bfloat162 q01 = __floats2bfloat162_rn(p0 - __low2float(h01),
                                                           p1 - __high2float(h01));
                __nv_bfloat162 q23 = __floats2bfloat162_rn(p2 - __low2float(h23),
                                                           p3 - __high2float(h23));
                aL[kc][2 * e]     = b2u(q01);
                aL[kc][2 * e + 1] = b2u(q23);
            }
        }
        rs0 += __shfl_xor_sync(0xffffffffu, rs0, 1);
        rs0 += __shfl_xor_sync(0xffffffffu, rs0, 2);
        rs1 += __shfl_xor_sync(0xffffffffu, rs1, 1);
        rs1 += __shfl_xor_sync(0xffffffffu, rs1, 2);
        l0 += rs0; l1 += rs1;

        // ---- Y += P V  (Ph*Vh + Ph*Vl + Pl*Vh) ----
        const int vr = ((lane >> 3) & 1) * 8 + (lane & 7);
        const int vc = (lane >> 4) * 8;
#pragma unroll
        for (int kc = 0; kc < 8; kc++) {
#pragma unroll
            for (int p = 0; p < 4; p++) {
                uint32_t off = SWZ((kc * 16 + vr) * 128 + (p * 16 + vc) * 2);
                uint32_t vh4[4], vl4[4];
                ldm4t(vh4, VhB + off);
                ldm4t(vl4, VlB + off);
                mma_bf16(yacc[2 * p], aH[kc], vh4[0], vh4[1]);
                mma_bf16(yacc[2 * p], aH[kc], vl4[0], vl4[1]);
                mma_bf16(yacc[2 * p], aL[kc], vh4[0], vh4[1]);
                mma_bf16(yacc[2 * p + 1], aH[kc], vh4[2], vh4[3]);
                mma_bf16(yacc[2 * p + 1], aH[kc], vl4[2], vl4[3]);
                mma_bf16(yacc[2 * p + 1], aL[kc], vh4[2], vh4[3]);
            }
        }
        __syncthreads();
    }

    // epilogue: normalize, split hi/lo, write [B,S,D]
    const float il0 = 1.0f / l0, il1 = 1.0f / l1;
    const int b = bh / HV, h = bh % HV;
    const int gr0 = qt * 128 + w * 16 + (lane >> 2);
    const size_t o0 = ((size_t)(b * SV) + gr0) * DV + h * KD;
    const size_t o1 = o0 + (size_t)8 * DV;
#pragma unroll
    for (int p = 0; p < 8; p++) {
        int c = p * 8 + (lane & 3) * 2;
        float y0 = yacc[p][0] * il0, y1 = yacc[p][1] * il0;
        float y2 = yacc[p][2] * il1, y3 = yacc[p][3] * il1;
        __nv_bfloat162 h0 = __floats2bfloat162_rn(y0, y1);
        __nv_bfloat162 h1 = __floats2bfloat162_rn(y2, y3);
        __nv_bfloat162 q0 = __floats2bfloat162_rn(y0 - __low2float(h0), y1 - __high2float(h0));
        __nv_bfloat162 q1 = __floats2bfloat162_rn(y2 - __low2float(h1), y3 - __high2float(h1));
        *(__nv_bfloat162*)(yhp + o0 + c) = h0;
        *(__nv_bfloat162*)(yhp + o1 + c) = h1;
        *(__nv_bfloat162*)(ylp + o0 + c) = q0;
        *(__nv_bfloat162*)(ylp + o1 + c) = q1;
    }
}

// ---------------------------------------------------------------------------
// kernel_launch
// ---------------------------------------------------------------------------
extern "C" void kernel_launch(void* const* d_in, const int* in_sizes, int n_in,
                              void* d_out, int out_size) {
    (void)in_sizes; (void)n_in; (void)out_size;
    const float* x  = (const float*)d_in[0];
    const float* Wq = (const float*)d_in[2];
    const float* Wk = (const float*)d_in[3];
    const float* Wv = (const float*)d_in[4];
    const float* Wo = (const float*)d_in[5];
    float* out = (float*)d_out;

    float* qkv;
    __nv_bfloat16 *xh, *xl, *wh, *wl, *qh, *ql, *kh, *kl, *vh, *vl, *yh, *yl;
    cudaGetSymbolAddress((void**)&qkv, g_qkv);
    cudaGetSymbolAddress((void**)&xh, g_xh);
    cudaGetSymbolAddress((void**)&xl, g_xl);
    cudaGetSymbolAddress((void**)&wh, g_wh);
    cudaGetSymbolAddress((void**)&wl, g_wl);
    cudaGetSymbolAddress((void**)&qh, g_qh);
    cudaGetSymbolAddress((void**)&ql, g_ql);
    cudaGetSymbolAddress((void**)&kh, g_kh);
    cudaGetSymbolAddress((void**)&kl, g_kl);
    cudaGetSymbolAddress((void**)&vh, g_vh);
    cudaGetSymbolAddress((void**)&vl, g_vl);
    cudaGetSymbolAddress((void**)&yh, g_yh);
    cudaGetSymbolAddress((void**)&yl, g_yl);

    cudaFuncSetAttribute(mma_gemm, cudaFuncAttributeMaxDynamicSharedMemorySize, GEMM_SMEM);
    cudaFuncSetAttribute(flash_mma, cudaFuncAttributeMaxDynamicSharedMemorySize, FA_SMEM);

    int n4 = MROWS * DV / 4;
    split_kernel<<<(n4 + 255) / 256, 256>>>(x, xh, xl, n4);

    dim3 tgrid(DV / 32, DV / 32);
    dim3 tblk(32, 8);
    trans_split_kernel<<<tgrid, tblk>>>(Wq, wh + 0 * DV * DV, wl + 0 * DV * DV, 0.125f);
    trans_split_kernel<<<tgrid, tblk>>>(Wk, wh + 1 * DV * DV, wl + 1 * DV * DV, 1.0f);
    trans_split_kernel<<<tgrid, tblk>>>(Wv, wh + 2 * DV * DV, wl + 2 * DV * DV, 1.0f);
    trans_split_kernel<<<tgrid, tblk>>>(Wo, wh + 3 * DV * DV, wl + 3 * DV * DV, 1.0f);

    // fused QKV projection: N = 3072
    dim3 qkvgrid(3 * DV / GBN, MROWS / GBM);   // (24, 32)
    mma_gemm<<<qkvgrid, 256, GEMM_SMEM>>>(xh, xl, wh, wl, qkv, 3 * DV);

    // rope + split + head-major repack
    int rthreads = 3 * BV * HV * SV * 16;
    rope_split_kernel<<<rthreads / 256, 256>>>(qkv, qh, ql, kh, kl, vh, vl);

    // tensor-core flash attention
    dim3 fgrid(SV / 128, BV * HV);             // (16, 32)
    flash_mma<<<fgrid, 256, FA_SMEM>>>(qh, ql, kh, kl, vh, vl, yh, yl);

    // output projection
    dim3 ogrid(DV / GBN, MROWS / GBM);         // (8, 32)
    mma_gemm<<<ogrid, 256, GEMM_SMEM>>>(yh, yl, wh + 3 * DV * DV, wl + 3 * DV * DV, out, DV);
}

// round 5
// speedup vs baseline: 3.8691x; 1.2638x over previous
#include <cuda_runtime.h>
#include <cuda_fp16.h>
#include <math.h>
#include <stdint.h>
#include <string.h>

// ---------------------------------------------------------------------------
// Problem constants: B=2, S=2048, D=1024, H=16, head_dim=64, rope dims=32
// ---------------------------------------------------------------------------
#define BV 2
#define HV 16
#define SV 2048
#define DV 1024
#define KD 64
#define MROWS (BV*SV)        // 4096
#define HEADROWS (BV*HV*SV)  // 65536

// Scratch (device globals: allocation-free rule)
__device__ float g_qkv[MROWS * 3 * DV];
__device__ __half g_xh[MROWS * DV];
__device__ __half g_xl[MROWS * DV];
__device__ __half g_wh[4 * DV * DV];
__device__ __half g_wl[4 * DV * DV];
__device__ __half g_qh[HEADROWS * KD];
__device__ __half g_ql[HEADROWS * KD];
__device__ __half g_kh[HEADROWS * KD];
__device__ __half g_kl[HEADROWS * KD];
__device__ __half g_vh[HEADROWS * KD];
__device__ __half g_vl[HEADROWS * KD];
__device__ __half g_yh[MROWS * DV];
__device__ __half g_yl[MROWS * DV];

// ---------------------------------------------------------------------------
// helpers
// ---------------------------------------------------------------------------
__device__ __forceinline__ uint32_t smem_u32(const void* p) {
    uint32_t a;
    asm("{ .reg .u64 t; cvta.to.shared.u64 t, %1; cvt.u32.u64 %0, t; }"
        : "=r"(a) : "l"(p));
    return a;
}

#define SWZ(o) ((o) ^ (((o) >> 3) & 0x70))

__device__ __forceinline__ void ldm4(uint32_t* r, uint32_t addr) {
    asm volatile("ldmatrix.sync.aligned.m8n8.x4.shared.b16 {%0,%1,%2,%3}, [%4];"
                 : "=r"(r[0]), "=r"(r[1]), "=r"(r[2]), "=r"(r[3]) : "r"(addr));
}

__device__ __forceinline__ void ldm4t(uint32_t* r, uint32_t addr) {
    asm volatile("ldmatrix.sync.aligned.m8n8.x4.trans.shared.b16 {%0,%1,%2,%3}, [%4];"
                 : "=r"(r[0]), "=r"(r[1]), "=r"(r[2]), "=r"(r[3]) : "r"(addr));
}

// f32-accumulate fp16 mma (main hi*hi pass)
__device__ __forceinline__ void mma_f32(float* c, const uint32_t* a,
                                        uint32_t b0, uint32_t b1) {
    asm volatile(
        "mma.sync.aligned.m16n8k16.row.col.f32.f16.f16.f32 "
        "{%0,%1,%2,%3},{%4,%5,%6,%7},{%8,%9},{%0,%1,%2,%3};"
        : "+f"(c[0]), "+f"(c[1]), "+f"(c[2]), "+f"(c[3])
        : "r"(a[0]), "r"(a[1]), "r"(a[2]), "r"(a[3]), "r"(b0), "r"(b1));
}

// f16-accumulate fp16 mma (correction passes, 2x rate)
__device__ __forceinline__ void mma_f16a(uint32_t* c, const uint32_t* a,
                                         uint32_t b0, uint32_t b1) {
    asm volatile(
        "mma.sync.aligned.m16n8k16.row.col.f16.f16.f16.f16 "
        "{%0,%1},{%2,%3,%4,%5},{%6,%7},{%0,%1};"
        : "+r"(c[0]), "+r"(c[1])
        : "r"(a[0]), "r"(a[1]), "r"(a[2]), "r"(a[3]), "r"(b0), "r"(b1));
}

__device__ __forceinline__ void cp16(uint32_t saddr, const void* gaddr) {
    asm volatile("cp.async.cg.shared.global [%0], [%1], 16;"
                 :: "r"(saddr), "l"(gaddr) : "memory");
}
#define CP_COMMIT() asm volatile("cp.async.commit_group;" ::: "memory")
#define CP_WAIT1()  asm volatile("cp.async.wait_group 1;" ::: "memory")
#define CP_WAIT0()  asm volatile("cp.async.wait_group 0;" ::: "memory")

__device__ __forceinline__ uint32_t b2u(__half2 v) {
    uint32_t u;
    memcpy(&u, &v, 4);
    return u;
}

__device__ __forceinline__ float2 h2f2(uint32_t u) {
    __half2 h;
    memcpy(&h, &u, 4);
    return __half22float2(h);
}

// ---------------------------------------------------------------------------
// Elementwise hi/lo fp16 split of x
// ---------------------------------------------------------------------------
__global__ void split_kernel(const float* __restrict__ src,
                             __half* __restrict__ hi,
                             __half* __restrict__ lo, int n4) {
    int i = blockIdx.x * blockDim.x + threadIdx.x;
    if (i >= n4) return;
    float4 v = ((const float4*)src)[i];
    __half2 hh0 = __floats2half2_rn(v.x, v.y);
    __half2 hh1 = __floats2half2_rn(v.z, v.w);
    __half2 ll0 = __floats2half2_rn(v.x - __low2float(hh0), v.y - __high2float(hh0));
    __half2 ll1 = __floats2half2_rn(v.z - __low2float(hh1), v.w - __high2float(hh1));
    *(__half2*)(hi + 4 * i)     = hh0;
    *(__half2*)(hi + 4 * i + 2) = hh1;
    *(__half2*)(lo + 4 * i)     = ll0;
    *(__half2*)(lo + 4 * i + 2) = ll1;
}

// ---------------------------------------------------------------------------
// Fused weight transpose + scale + split for all 4 weights (blockIdx.z picks)
// ---------------------------------------------------------------------------
__global__ void trans_split4_kernel(const float* __restrict__ W0,
                                    const float* __restrict__ W1,
                                    const float* __restrict__ W2,
                                    const float* __restrict__ W3,
                                    __half* __restrict__ hi_all,
                                    __half* __restrict__ lo_all) {
    __shared__ float tile[32][33];
    const float* Ws[4] = { W0, W1, W2, W3 };
    const float* W = Ws[blockIdx.z];
    const float scale = (blockIdx.z == 0) ? 0.125f : 1.0f;
    __half* hi = hi_all + (size_t)blockIdx.z * DV * DV;
    __half* lo = lo_all + (size_t)blockIdx.z * DV * DV;

    int bx = blockIdx.x * 32, by = blockIdx.y * 32;
    int tx = threadIdx.x, ty = threadIdx.y;
#pragma unroll
    for (int r = 0; r < 32; r += 8)
        tile[ty + r][tx] = W[(size_t)(by + ty + r) * DV + bx + tx];
    __syncthreads();
#pragma unroll
    for (int r = 0; r < 32; r += 8) {
        float v = tile[tx][ty + r] * scale;
        __half h = __float2half_rn(v);
        size_t o = (size_t)(bx + ty + r) * DV + by + tx;
        hi[o] = h;
        lo[o] = __float2half_rn(v - __half2float(h));
    }
}

// ---------------------------------------------------------------------------
// fp16x3 emulated-fp32 GEMM: C[M x N] = A[M x K=DV] @ BT[N x K]^T.
// hi*hi in f32-acc mma; (hi*lo + lo*hi) in f16-acc mma (2x rate).
// 128x128 block tile, BK=64, cp.async double buffer, 8 warps.
// ---------------------------------------------------------------------------
#define GBM 128
#define GBN 128
#define GBK 64
#define TILE_BYTES (GBM * GBK * 2)
#define STAGE_BYTES (4 * TILE_BYTES)
#define GEMM_SMEM (2 * STAGE_BYTES)
#define NITER (DV / GBK)

__global__ __launch_bounds__(256, 1)
void mma_gemm(const __half* __restrict__ Ah,
              const __half* __restrict__ Al,
              const __half* __restrict__ Bh,
              const __half* __restrict__ Bl,
              float* __restrict__ C, int ldc) {
    extern __shared__ __align__(1024) char sm[];
    const uint32_t sb = smem_u32(sm);
    const int t = threadIdx.x;
    const int lane = t & 31, wid = t >> 5;
    const int warpM = wid & 3, warpN = wid >> 2;
    const int row0 = blockIdx.y * GBM;
    const int col0 = blockIdx.x * GBN;

    const __half* srcs[4] = {
        Ah + (size_t)row0 * DV, Al + (size_t)row0 * DV,
        Bh + (size_t)col0 * DV, Bl + (size_t)col0 * DV };

    const int cm = t >> 3;
    const int cc = t & 7;

    float accF[2][8][4];
    uint32_t accC[2][8][2];
#pragma unroll
    for (int i = 0; i < 2; i++)
#pragma unroll
        for (int j = 0; j < 8; j++) {
#pragma unroll
            for (int r = 0; r < 4; r++) accF[i][j][r] = 0.0f;
            accC[i][j][0] = 0u; accC[i][j][1] = 0u;
        }

    const int sub = lane >> 3, l7 = lane & 7;
    const int rowA0 = warpM * 32 + ((sub & 1) << 3) + l7;
    const int rowA1 = rowA0 + 16;
    const int kA = (sub >> 1);
    int rowB[4];
#pragma unroll
    for (int p = 0; p < 4; p++)
        rowB[p] = warpN * 64 + p * 16 + ((sub >> 1) << 3) + l7;
    const int kB = (sub & 1);

    {
#pragma unroll
        for (int tile = 0; tile < 4; tile++) {
#pragma unroll
            for (int j = 0; j < 4; j++) {
                int m = cm + 32 * j;
                cp16(sb + tile * TILE_BYTES + SWZ(m * 128 + cc * 16),
                     srcs[tile] + (size_t)m * DV + cc * 8);
            }
        }
        CP_COMMIT();
    }

    for (int it = 0; it < NITER; it++) {
        const int buf = it & 1;
        __syncthreads();
        if (it + 1 < NITER) {
            const int k0 = (it + 1) * GBK;
            const uint32_t stb = sb + ((it + 1) & 1) * STAGE_BYTES;
#pragma unroll
            for (int tile = 0; tile < 4; tile++) {
#pragma unroll
                for (int j = 0; j < 4; j++) {
                    int m = cm + 32 * j;
                    cp16(stb + tile * TILE_BYTES + SWZ(m * 128 + cc * 16),
                         srcs[tile] + (size_t)m * DV + k0 + cc * 8);
                }
            }
            CP_COMMIT();
            CP_WAIT1();
        } else {
            CP_WAIT0();
        }
        __syncthreads();

        const uint32_t ahB = sb + buf * STAGE_BYTES;
        const uint32_t alB = ahB + TILE_BYTES;
        const uint32_t bhB = ahB + 2 * TILE_BYTES;
        const uint32_t blB = ahB + 3 * TILE_BYTES;

#pragma unroll
        for (int ks = 0; ks < 4; ks++) {
            const int kcA = ks * 2 + kA;
            const int kcB = ks * 2 + kB;
            uint32_t ah[2][4], al[2][4];
            ldm4(ah[0], ahB + SWZ(rowA0 * 128 + kcA * 16));
            ldm4(ah[1], ahB + SWZ(rowA1 * 128 + kcA * 16));
            ldm4(al[0], alB + SWZ(rowA0 * 128 + kcA * 16));
            ldm4(al[1], alB + SWZ(rowA1 * 128 + kcA * 16));
            uint32_t bh[4][4], bl[4][4];
#pragma unroll
            for (int p = 0; p < 4; p++) {
                ldm4(bh[p], bhB + SWZ(rowB[p] * 128 + kcB * 16));
                ldm4(bl[p], blB + SWZ(rowB[p] * 128 + kcB * 16));
            }
#pragma unroll
            for (int mt = 0; mt < 2; mt++) {
#pragma unroll
                for (int nt = 0; nt < 8; nt++) {
                    const int p = nt >> 1, o = (nt & 1) * 2;
                    mma_f32(accF[mt][nt], ah[mt], bh[p][o], bh[p][o + 1]);
                    mma_f16a(accC[mt][nt], ah[mt], bl[p][o], bl[p][o + 1]);
                    mma_f16a(accC[mt][nt], al[mt], bh[p][o], bh[p][o + 1]);
                }
            }
        }
    }

#pragma unroll
    for (int mt = 0; mt < 2; mt++) {
#pragma unroll
        for (int nt = 0; nt < 8; nt++) {
            float2 c0 = h2f2(accC[mt][nt][0]);
            float2 c1 = h2f2(accC[mt][nt][1]);
            int r = row0 + warpM * 32 + mt * 16 + (lane >> 2);
            int c = col0 + warpN * 64 + nt * 8 + (lane & 3) * 2;
            *(float2*)(C + (size_t)r * ldc + c) =
                make_float2(accF[mt][nt][0] + c0.x, accF[mt][nt][1] + c0.y);
            *(float2*)(C + (size_t)(r + 8) * ldc + c) =
                make_float2(accF[mt][nt][2] + c1.x, accF[mt][nt][3] + c1.y);
        }
    }
}

// ---------------------------------------------------------------------------
// RoPE + hi/lo fp16 split + repack to head-major [B,H,S,64].
// ---------------------------------------------------------------------------
__global__ void rope_split_kernel(const float* __restrict__ qkv,
                                  __half* __restrict__ qh, __half* __restrict__ ql,
                                  __half* __restrict__ kh, __half* __restrict__ kl,
                                  __half* __restrict__ vh, __half* __restrict__ vl) {
    int idx = blockIdx.x * blockDim.x + threadIdx.x;
    int lane16 = idx & 15;
    int row = idx >> 4;
    int s = row % SV;
    int r2 = row / SV;
    int bh = r2 % (BV * HV);
    int tt = r2 / (BV * HV);            // 0=q, 1=k, 2=v
    int b = bh / HV, h = bh % HV;

    const float* src = qkv + ((size_t)(b * SV + s)) * (3 * DV) + tt * DV + h * KD + lane16 * 4;
    float4 v = *(const float4*)src;

    if (tt < 2 && lane16 < 8) {
        int i0 = lane16 * 2;
        float inv0 = powf(10000.0f, -(float)i0 / 16.0f);
        float inv1 = powf(10000.0f, -(float)(i0 + 1) / 16.0f);
        float sn0, cs0, sn1, cs1;
        sincosf((float)s * inv0, &sn0, &cs0);
        sincosf((float)s * inv1, &sn1, &cs1);
        float a = v.x * cs0 - v.y * sn0;
        float bq = v.y * cs0 + v.x * sn0;
        float c = v.z * cs1 - v.w * sn1;
        float d = v.w * cs1 + v.z * sn1;
        v = make_float4(a, bq, c, d);
    }

    __half* dh = (tt == 0) ? qh : (tt == 1) ? kh : vh;
    __half* dl = (tt == 0) ? ql : (tt == 1) ? kl : vl;
    size_t o = ((size_t)bh * SV + s) * KD + lane16 * 4;

    __half2 h0 = __floats2half2_rn(v.x, v.y);
    __half2 h1 = __floats2half2_rn(v.z, v.w);
    __half2 l0 = __floats2half2_rn(v.x - __low2float(h0), v.y - __high2float(h0));
    __half2 l1 = __floats2half2_rn(v.z - __low2float(h1), v.w - __high2float(h1));
    *(__half2*)(dh + o)     = h0;
    *(__half2*)(dh + o + 2) = h1;
    *(__half2*)(dl + o)     = l0;
    *(__half2*)(dl + o + 2) = l1;
}

// ---------------------------------------------------------------------------
// Tensor-core causal flash attention (fp16x3 QK and PV, fp32 softmax).
// grid = (S/128, B*H), 256 threads (8 warps), warp owns 16 query rows.
// ---------------------------------------------------------------------------
#define FA_SMEM (32768 + 2 * 65536)

__device__ __forceinline__ void fa_load_kv(
    uint32_t base, const __half* kh, const __half* kl,
    const __half* vh, const __half* vl,
    int kt, int cm, int cc) {
    const __half* srcs[4] = { kh, kl, vh, vl };
#pragma unroll
    for (int tt = 0; tt < 4; tt++) {
#pragma unroll
        for (int j = 0; j < 4; j++) {
            int r = cm + 32 * j;
            cp16(base + tt * 16384 + SWZ(r * 128 + cc * 16),
                 srcs[tt] + (size_t)(kt * 128 + r) * KD + cc * 8);
        }
    }
    CP_COMMIT();
}

__global__ __launch_bounds__(256, 1)
void flash_mma(const __half* __restrict__ qh, const __half* __restrict__ ql,
               const __half* __restrict__ kh, const __half* __restrict__ kl,
               const __half* __restrict__ vh, const __half* __restrict__ vl,
               __half* __restrict__ yhp, __half* __restrict__ ylp) {
    extern __shared__ __align__(1024) char sm[];
    const uint32_t sb = smem_u32(sm);
    const int t = threadIdx.x, lane = t & 31, w = t >> 5;
    const int qt = blockIdx.x, bh = blockIdx.y;
    const size_t ho = (size_t)bh * SV * KD;

    const int cm = t >> 3, cc = t & 7;

    {
        const __half* qsrc[2] = { qh + ho + (size_t)qt * 128 * KD,
                                  ql + ho + (size_t)qt * 128 * KD };
#pragma unroll
        for (int tt = 0; tt < 2; tt++) {
#pragma unroll
            for (int j = 0; j < 4; j++) {
                int r = cm + 32 * j;
                cp16(sb + tt * 16384 + SWZ(r * 128 + cc * 16),
                     qsrc[tt] + (size_t)r * KD + cc * 8);
            }
        }
        CP_COMMIT();
    }
    fa_load_kv(sb + 32768, kh + ho, kl + ho, vh + ho, vl + ho, 0, cm, cc);

    const int nt = qt + 1;
    const int sub = lane >> 3, l7 = lane & 7;

    uint32_t qfh[4][4], qfl[4][4];
    float m0 = -3.0e38f, m1 = -3.0e38f, l0 = 0.0f, l1 = 0.0f;
    float yacc[8][4];
#pragma unroll
    for (int p = 0; p < 8; p++)
#pragma unroll
        for (int e = 0; e < 4; e++) yacc[p][e] = 0.0f;

    for (int kt = 0; kt < nt; kt++) {
        const int st = kt & 1;
        CP_WAIT0();
        __syncthreads();

        if (kt == 0) {
            const int rA = w * 16 + ((sub & 1) << 3) + l7;
            const int kA = sub >> 1;
#pragma unroll
            for (int kc = 0; kc < 4; kc++) {
                uint32_t off = SWZ(rA * 128 + (kc * 2 + kA) * 16);
                ldm4(qfh[kc], sb + off);
                ldm4(qfl[kc], sb + 16384 + off);
            }
        }
        if (kt + 1 < nt)
            fa_load_kv(sb + 32768 + (st ^ 1) * 65536,
                       kh + ho, kl + ho, vh + ho, vl + ho, kt + 1, cm, cc);

        const uint32_t KhB = sb + 32768 + st * 65536;
        const uint32_t KlB = KhB + 16384;
        const uint32_t VhB = KhB + 32768;
        const uint32_t VlB = KhB + 49152;

        // ---- S = Q K^T : hi*hi f32-acc; corrections f16-acc ----
        float sacc[16][4];
        uint32_t cacc[16][2];
#pragma unroll
        for (int n8 = 0; n8 < 16; n8++) {
#pragma unroll
            for (int e = 0; e < 4; e++) sacc[n8][e] = 0.0f;
            cacc[n8][0] = 0u; cacc[n8][1] = 0u;
        }

        const int rB = ((sub >> 1) << 3) + l7;
        const int kB = sub & 1;
#pragma unroll
        for (int kc = 0; kc < 4; kc++) {
#pragma unroll
            for (int p = 0; p < 8; p++) {
                uint32_t off = SWZ((p * 16 + rB) * 128 + (kc * 2 + kB) * 16);
                uint32_t kh4[4], kl4[4];
                ldm4(kh4, KhB + off);
                ldm4(kl4, KlB + off);
                mma_f32(sacc[2 * p], qfh[kc], kh4[0], kh4[1]);
                mma_f16a(cacc[2 * p], qfh[kc], kl4[0], kl4[1]);
                mma_f16a(cacc[2 * p], qfl[kc], kh4[0], kh4[1]);
                mma_f32(sacc[2 * p + 1], qfh[kc], kh4[2], kh4[3]);
                mma_f16a(cacc[2 * p + 1], qfh[kc], kl4[2], kl4[3]);
                mma_f16a(cacc[2 * p + 1], qfl[kc], kh4[2], kh4[3]);
            }
        }
        // fold f16 corrections into f32 scores
#pragma unroll
        for (int n8 = 0; n8 < 16; n8++) {
            float2 c0 = h2f2(cacc[n8][0]);
            float2 c1 = h2f2(cacc[n8][1]);
            sacc[n8][0] += c0.x; sacc[n8][1] += c0.y;
            sacc[n8][2] += c1.x; sacc[n8][3] += c1.y;
        }

        // causal mask on diagonal tile
        const int rr0 = w * 16 + (lane >> 2);
        if (kt == qt) {
#pragma unroll
            for (int n8 = 0; n8 < 16; n8++) {
                int cb = n8 * 8 + (lane & 3) * 2;
                if (cb     > rr0)     sacc[n8][0] = -1e30f;
                if (cb + 1 > rr0)     sacc[n8][1] = -1e30f;
                if (cb     > rr0 + 8) sacc[n8][2] = -1e30f;
                if (cb + 1 > rr0 + 8) sacc[n8][3] = -1e30f;
            }
        }

        // ---- online softmax ----
        float mx0 = -3.0e38f, mx1 = -3.0e38f;
#pragma unroll
        for (int n8 = 0; n8 < 16; n8++) {
            mx0 = fmaxf(mx0, fmaxf(sacc[n8][0], sacc[n8][1]));
            mx1 = fmaxf(mx1, fmaxf(sacc[n8][2], sacc[n8][3]));
        }
        mx0 = fmaxf(mx0, __shfl_xor_sync(0xffffffffu, mx0, 1));
        mx0 = fmaxf(mx0, __shfl_xor_sync(0xffffffffu, mx0, 2));
        mx1 = fmaxf(mx1, __shfl_xor_sync(0xffffffffu, mx1, 1));
        mx1 = fmaxf(mx1, __shfl_xor_sync(0xffffffffu, mx1, 2));
        const float mt0 = fmaxf(m0, mx0), mt1 = fmaxf(m1, mx1);
        const float sc0 = __expf(m0 - mt0), sc1 = __expf(m1 - mt1);
        l0 *= sc0; l1 *= sc1;
#pragma unroll
        for (int p = 0; p < 8; p++) {
            yacc[p][0] *= sc0; yacc[p][1] *= sc0;
            yacc[p][2] *= sc1; yacc[p][3] *= sc1;
        }
        m0 = mt0; m1 = mt1;

        // p = exp(s - m), split to hi/lo fp16 A-fragments
        uint32_t aH[8][4], aL[8][4];
        float rs0 = 0.0f, rs1 = 0.0f;
#pragma unroll
        for (int kc = 0; kc < 8; kc++) {
#pragma unroll
            for (int e = 0; e < 2; e++) {
                const int n8 = 2 * kc + e;
                float p0 = __expf(sacc[n8][0] - mt0);
                float p1 = __expf(sacc[n8][1] - mt0);
                float p2 = __expf(sacc[n8][2] - mt1);
                float p3 = __expf(sacc[n8][3] - mt1);
                rs0 += p0 + p1; rs1 += p2 + p3;
                __half2 h01 = __floats2half2_rn(p0, p1);
                __half2 h23 = __floats2half2_rn(p2, p3);
                aH[kc][2 * e]     = b2u(h01);
                aH[kc][2 * e + 1] = b2u(h23);
                __half2 q01 = __floats2half2_rn(p0 - __low2float(h01),
                                                p1 - __high2float(h01));
                __half2 q23 = __floats2half2_rn(p2 - __low2float(h23),
                                                p3 - __high2float(h23));
                aL[kc][2 * e]     = b2u(q01);
                aL[kc][2 * e + 1] = b2u(q23);
            }
        }
        rs0 += __shfl_xor_sync(0xffffffffu, rs0, 1);
        rs0 += __shfl_xor_sync(0xffffffffu, rs0, 2);
        rs1 += __shfl_xor_sync(0xffffffffu, rs1, 1);
        rs1 += __shfl_xor_sync(0xffffffffu, rs1, 2);
        l0 += rs0; l1 += rs1;

        // ---- Y += P V : hi*hi f32-acc; corrections f16-acc ----
        uint32_t ycc[8][2];
#pragma unroll
        for (int p = 0; p < 8; p++) { ycc[p][0] = 0u; ycc[p][1] = 0u; }

        const int vr = ((lane >> 3) & 1) * 8 + (lane & 7);
        const int vc = (lane >> 4) * 8;
#pragma unroll
        for (int kc = 0; kc < 8; kc++) {
#pragma unroll
            for (int p = 0; p < 4; p++) {
                uint32_t off = SWZ((kc * 16 + vr) * 128 + (p * 16 + vc) * 2);
                uint32_t vh4[4], vl4[4];
                ldm4t(vh4, VhB + off);
                ldm4t(vl4, VlB + off);
                mma_f32(yacc[2 * p], aH[kc], vh4[0], vh4[1]);
                mma_f16a(ycc[2 * p], aH[kc], vl4[0], vl4[1]);
                mma_f16a(ycc[2 * p], aL[kc], vh4[0], vh4[1]);
                mma_f32(yacc[2 * p + 1], aH[kc], vh4[2], vh4[3]);
                mma_f16a(ycc[2 * p + 1], aH[kc], vl4[2], vl4[3]);
                mma_f16a(ycc[2 * p + 1], aL[kc], vh4[2], vh4[3]);
            }
        }
        // fold PV corrections (before next iteration's rescale)
#pragma unroll
        for (int p = 0; p < 8; p++) {
            float2 c0 = h2f2(ycc[p][0]);
            float2 c1 = h2f2(ycc[p][1]);
            yacc[p][0] += c0.x; yacc[p][1] += c0.y;
            yacc[p][2] += c1.x; yacc[p][3] += c1.y;
        }
        __syncthreads();
    }

    // epilogue: normalize, split hi/lo, write [B,S,D]
    const float il0 = 1.0f / l0, il1 = 1.0f / l1;
    const int b = bh / HV, h = bh % HV;
    const int gr0 = qt * 128 + w * 16 + (lane >> 2);
    const size_t o0 = ((size_t)(b * SV) + gr0) * DV + h * KD;
    const size_t o1 = o0 + (size_t)8 * DV;
#pragma unroll
    for (int p = 0; p < 8; p++) {
        int c = p * 8 + (lane & 3) * 2;
        float y0 = yacc[p][0] * il0, y1 = yacc[p][1] * il0;
        float y2 = yacc[p][2] * il1, y3 = yacc[p][3] * il1;
        __half2 h0 = __floats2half2_rn(y0, y1);
        __half2 h1 = __floats2half2_rn(y2, y3);
        __half2 q0 = __floats2half2_rn(y0 - __low2float(h0), y1 - __high2float(h0));
        __half2 q1 = __floats2half2_rn(y2 - __low2float(h1), y3 - __high2float(h1));
        *(__half2*)(yhp + o0 + c) = h0;
        *(__half2*)(yhp + o1 + c) = h1;
        *(__half2*)(ylp + o0 + c) = q0;
        *(__half2*)(ylp + o1 + c) = q1;
    }
}

// ---------------------------------------------------------------------------
// kernel_launch
// ---------------------------------------------------------------------------
extern "C" void kernel_launch(void* const* d_in, const int* in_sizes, int n_in,
                              void* d_out, int out_size) {
    (void)in_sizes; (void)n_in; (void)out_size;
    const float* x  = (const float*)d_in[0];
    const float* Wq = (const float*)d_in[2];
    const float* Wk = (const float*)d_in[3];
    const float* Wv = (const float*)d_in[4];
    const float* Wo = (const float*)d_in[5];
    float* out = (float*)d_out;

    float* qkv;
    __half *xh, *xl, *wh, *wl, *qh, *ql, *kh, *kl, *vh, *vl, *yh, *yl;
    cudaGetSymbolAddress((void**)&qkv, g_qkv);
    cudaGetSymbolAddress((void**)&xh, g_xh);
    cudaGetSymbolAddress((void**)&xl, g_xl);
    cudaGetSymbolAddress((void**)&wh, g_wh);
    cudaGetSymbolAddress((void**)&wl, g_wl);
    cudaGetSymbolAddress((void**)&qh, g_qh);
    cudaGetSymbolAddress((void**)&ql, g_ql);
    cudaGetSymbolAddress((void**)&kh, g_kh);
    cudaGetSymbolAddress((void**)&kl, g_kl);
    cudaGetSymbolAddress((void**)&vh, g_vh);
    cudaGetSymbolAddress((void**)&vl, g_vl);
    cudaGetSymbolAddress((void**)&yh, g_yh);
    cudaGetSymbolAddress((void**)&yl, g_yl);

    cudaFuncSetAttribute(mma_gemm, cudaFuncAttributeMaxDynamicSharedMemorySize, GEMM_SMEM);
    cudaFuncSetAttribute(flash_mma, cudaFuncAttributeMaxDynamicSharedMemorySize, FA_SMEM);

    int n4 = MROWS * DV / 4;
    split_kernel<<<(n4 + 255) / 256, 256>>>(x, xh, xl, n4);

    dim3 tgrid(DV / 32, DV / 32, 4);
    dim3 tblk(32, 8);
    trans_split4_kernel<<<tgrid, tblk>>>(Wq, Wk, Wv, Wo, wh, wl);

    // fused QKV projection: N = 3072
    dim3 qkvgrid(3 * DV / GBN, MROWS / GBM);   // (24, 32)
    mma_gemm<<<qkvgrid, 256, GEMM_SMEM>>>(xh, xl, wh, wl, qkv, 3 * DV);

    // rope + split + head-major repack
    int rthreads = 3 * BV * HV * SV * 16;
    rope_split_kernel<<<rthreads / 256, 256>>>(qkv, qh, ql, kh, kl, vh, vl);

    // tensor-core flash attention
    dim3 fgrid(SV / 128, BV * HV);             // (16, 32)
    flash_mma<<<fgrid, 256, FA_SMEM>>>(qh, ql, kh, kl, vh, vl, yh, yl);

    // output projection
    dim3 ogrid(DV / GBN, MROWS / GBM);         // (8, 32)
    mma_gemm<<<ogrid, 256, GEMM_SMEM>>>(yh, yl, wh + 3 * (size_t)DV * DV, wl + 3 * (size_t)DV * DV, out, DV);
}

// round 6
// speedup vs baseline: 5.6965x; 1.4723x over previous
#include <cuda_runtime.h>
#include <cuda_fp16.h>
#include <math.h>
#include <stdint.h>
#include <string.h>

// ---------------------------------------------------------------------------
// Problem constants: B=2, S=2048, D=1024, H=16, head_dim=64, rope dims=32
// ---------------------------------------------------------------------------
#define BV 2
#define HV 16
#define SV 2048
#define DV 1024
#define KD 64
#define MROWS (BV*SV)        // 4096
#define HEADROWS (BV*HV*SV)  // 65536

// Scratch (device globals: allocation-free rule)
__device__ float g_qkv[MROWS * 3 * DV];
__device__ float g_rope[SV * 16 * 2];     // (sin, cos) per (s, pair)
__device__ __half g_xh[MROWS * DV];
__device__ __half g_wh[4 * DV * DV];
__device__ __half g_wl[4 * DV * DV];
__device__ __half g_qh[HEADROWS * KD];
__device__ __half g_kh[HEADROWS * KD];
__device__ __half g_kl[HEADROWS * KD];
__device__ __half g_vh[HEADROWS * KD];
__device__ __half g_vl[HEADROWS * KD];
__device__ __half g_yh[MROWS * DV];

// ---------------------------------------------------------------------------
// helpers
// ---------------------------------------------------------------------------
__device__ __forceinline__ uint32_t smem_u32(const void* p) {
    uint32_t a;
    asm("{ .reg .u64 t; cvta.to.shared.u64 t, %1; cvt.u32.u64 %0, t; }"
        : "=r"(a) : "l"(p));
    return a;
}

#define SWZ(o) ((o) ^ (((o) >> 3) & 0x70))

__device__ __forceinline__ void ldm4(uint32_t* r, uint32_t addr) {
    asm volatile("ldmatrix.sync.aligned.m8n8.x4.shared.b16 {%0,%1,%2,%3}, [%4];"
                 : "=r"(r[0]), "=r"(r[1]), "=r"(r[2]), "=r"(r[3]) : "r"(addr));
}

__device__ __forceinline__ void ldm4t(uint32_t* r, uint32_t addr) {
    asm volatile("ldmatrix.sync.aligned.m8n8.x4.trans.shared.b16 {%0,%1,%2,%3}, [%4];"
                 : "=r"(r[0]), "=r"(r[1]), "=r"(r[2]), "=r"(r[3]) : "r"(addr));
}

// f32-accumulate fp16 mma (main hi*hi pass)
__device__ __forceinline__ void mma_f32(float* c, const uint32_t* a,
                                        uint32_t b0, uint32_t b1) {
    asm volatile(
        "mma.sync.aligned.m16n8k16.row.col.f32.f16.f16.f32 "
        "{%0,%1,%2,%3},{%4,%5,%6,%7},{%8,%9},{%0,%1,%2,%3};"
        : "+f"(c[0]), "+f"(c[1]), "+f"(c[2]), "+f"(c[3])
        : "r"(a[0]), "r"(a[1]), "r"(a[2]), "r"(a[3]), "r"(b0), "r"(b1));
}

// f16-accumulate fp16 mma (correction pass, 2x rate)
__device__ __forceinline__ void mma_f16a(uint32_t* c, const uint32_t* a,
                                         uint32_t b0, uint32_t b1) {
    asm volatile(
        "mma.sync.aligned.m16n8k16.row.col.f16.f16.f16.f16 "
        "{%0,%1},{%2,%3,%4,%5},{%6,%7},{%0,%1};"
        : "+r"(c[0]), "+r"(c[1])
        : "r"(a[0]), "r"(a[1]), "r"(a[2]), "r"(a[3]), "r"(b0), "r"(b1));
}

__device__ __forceinline__ void cp16(uint32_t saddr, const void* gaddr) {
    asm volatile("cp.async.cg.shared.global [%0], [%1], 16;"
                 :: "r"(saddr), "l"(gaddr) : "memory");
}
#define CP_COMMIT() asm volatile("cp.async.commit_group;" ::: "memory")
#define CP_WAIT1()  asm volatile("cp.async.wait_group 1;" ::: "memory")
#define CP_WAIT0()  asm volatile("cp.async.wait_group 0;" ::: "memory")

__device__ __forceinline__ uint32_t b2u(__half2 v) {
    uint32_t u;
    memcpy(&u, &v, 4);
    return u;
}

__device__ __forceinline__ float2 h2f2(uint32_t u) {
    __half2 h;
    memcpy(&h, &u, 4);
    return __half22float2(h);
}

// ---------------------------------------------------------------------------
// fp32 -> fp16 convert of x (A-side needs hi only now)
// ---------------------------------------------------------------------------
__global__ void tohalf_kernel(const float* __restrict__ src,
                              __half* __restrict__ hi, int n4) {
    int i = blockIdx.x * blockDim.x + threadIdx.x;
    if (i >= n4) return;
    float4 v = ((const float4*)src)[i];
    *(__half2*)(hi + 4 * i)     = __floats2half2_rn(v.x, v.y);
    *(__half2*)(hi + 4 * i + 2) = __floats2half2_rn(v.z, v.w);
}

// ---------------------------------------------------------------------------
// RoPE sin/cos table: tbl[(s*16+i)*2] = sin(s*10000^(-i/16)), [..+1] = cos
// (same powf/sincosf arithmetic as the verified inline version)
// ---------------------------------------------------------------------------
__global__ void rope_table_kernel(float* __restrict__ tbl) {
    int idx = blockIdx.x * blockDim.x + threadIdx.x;
    if (idx >= SV * 16) return;
    int i = idx & 15, s = idx >> 4;
    float inv = powf(10000.0f, -(float)i / 16.0f);
    float sn, cs;
    sincosf((float)s * inv, &sn, &cs);
    tbl[2 * idx]     = sn;
    tbl[2 * idx + 1] = cs;
}

// ---------------------------------------------------------------------------
// Fused weight transpose + scale + split for all 4 weights (blockIdx.z picks)
// ---------------------------------------------------------------------------
__global__ void trans_split4_kernel(const float* __restrict__ W0,
                                    const float* __restrict__ W1,
                                    const float* __restrict__ W2,
                                    const float* __restrict__ W3,
                                    __half* __restrict__ hi_all,
                                    __half* __restrict__ lo_all) {
    __shared__ float tile[32][33];
    const float* Ws[4] = { W0, W1, W2, W3 };
    const float* W = Ws[blockIdx.z];
    const float scale = (blockIdx.z == 0) ? 0.125f : 1.0f;
    __half* hi = hi_all + (size_t)blockIdx.z * DV * DV;
    __half* lo = lo_all + (size_t)blockIdx.z * DV * DV;

    int bx = blockIdx.x * 32, by = blockIdx.y * 32;
    int tx = threadIdx.x, ty = threadIdx.y;
#pragma unroll
    for (int r = 0; r < 32; r += 8)
        tile[ty + r][tx] = W[(size_t)(by + ty + r) * DV + bx + tx];
    __syncthreads();
#pragma unroll
    for (int r = 0; r < 32; r += 8) {
        float v = tile[tx][ty + r] * scale;
        __half h = __float2half_rn(v);
        size_t o = (size_t)(bx + ty + r) * DV + by + tx;
        hi[o] = h;
        lo[o] = __float2half_rn(v - __half2float(h));
    }
}

// ---------------------------------------------------------------------------
// fp16x2 emulated GEMM: C = Ah @ (Bh + Bl)^T.
// hi*hi in f32-acc mma; Ah*Bl in f16-acc mma (2x rate).
// 128x128 block tile, BK=64, cp.async double buffer, 8 warps.
// ---------------------------------------------------------------------------
#define GBM 128
#define GBN 128
#define GBK 64
#define TILE_BYTES (GBM * GBK * 2)
#define STAGE_BYTES (3 * TILE_BYTES)      // Ah, Bh, Bl
#define GEMM_SMEM (2 * STAGE_BYTES)       // 98304
#define NITER (DV / GBK)

__global__ __launch_bounds__(256, 1)
void mma_gemm(const __half* __restrict__ Ah,
              const __half* __restrict__ Bh,
              const __half* __restrict__ Bl,
              float* __restrict__ C, int ldc) {
    extern __shared__ __align__(1024) char sm[];
    const uint32_t sb = smem_u32(sm);
    const int t = threadIdx.x;
    const int lane = t & 31, wid = t >> 5;
    const int warpM = wid & 3, warpN = wid >> 2;
    const int row0 = blockIdx.y * GBM;
    const int col0 = blockIdx.x * GBN;

    const __half* srcs[3] = {
        Ah + (size_t)row0 * DV,
        Bh + (size_t)col0 * DV, Bl + (size_t)col0 * DV };

    const int cm = t >> 3;
    const int cc = t & 7;

    float accF[2][8][4];
    uint32_t accC[2][8][2];
#pragma unroll
    for (int i = 0; i < 2; i++)
#pragma unroll
        for (int j = 0; j < 8; j++) {
#pragma unroll
            for (int r = 0; r < 4; r++) accF[i][j][r] = 0.0f;
            accC[i][j][0] = 0u; accC[i][j][1] = 0u;
        }

    const int sub = lane >> 3, l7 = lane & 7;
    const int rowA0 = warpM * 32 + ((sub & 1) << 3) + l7;
    const int rowA1 = rowA0 + 16;
    const int kA = (sub >> 1);
    int rowB[4];
#pragma unroll
    for (int p = 0; p < 4; p++)
        rowB[p] = warpN * 64 + p * 16 + ((sub >> 1) << 3) + l7;
    const int kB = (sub & 1);

    {
#pragma unroll
        for (int tile = 0; tile < 3; tile++) {
#pragma unroll
            for (int j = 0; j < 4; j++) {
                int m = cm + 32 * j;
                cp16(sb + tile * TILE_BYTES + SWZ(m * 128 + cc * 16),
                     srcs[tile] + (size_t)m * DV + cc * 8);
            }
        }
        CP_COMMIT();
    }

    for (int it = 0; it < NITER; it++) {
        const int buf = it & 1;
        __syncthreads();
        if (it + 1 < NITER) {
            const int k0 = (it + 1) * GBK;
            const uint32_t stb = sb + ((it + 1) & 1) * STAGE_BYTES;
#pragma unroll
            for (int tile = 0; tile < 3; tile++) {
#pragma unroll
                for (int j = 0; j < 4; j++) {
                    int m = cm + 32 * j;
                    cp16(stb + tile * TILE_BYTES + SWZ(m * 128 + cc * 16),
                         srcs[tile] + (size_t)m * DV + k0 + cc * 8);
                }
            }
            CP_COMMIT();
            CP_WAIT1();
        } else {
            CP_WAIT0();
        }
        __syncthreads();

        const uint32_t ahB = sb + buf * STAGE_BYTES;
        const uint32_t bhB = ahB + TILE_BYTES;
        const uint32_t blB = ahB + 2 * TILE_BYTES;

#pragma unroll
        for (int ks = 0; ks < 4; ks++) {
            const int kcA = ks * 2 + kA;
            const int kcB = ks * 2 + kB;
            uint32_t ah[2][4];
            ldm4(ah[0], ahB + SWZ(rowA0 * 128 + kcA * 16));
            ldm4(ah[1], ahB + SWZ(rowA1 * 128 + kcA * 16));
            uint32_t bh[4][4], bl[4][4];
#pragma unroll
            for (int p = 0; p < 4; p++) {
                ldm4(bh[p], bhB + SWZ(rowB[p] * 128 + kcB * 16));
                ldm4(bl[p], blB + SWZ(rowB[p] * 128 + kcB * 16));
            }
#pragma unroll
            for (int mt = 0; mt < 2; mt++) {
#pragma unroll
                for (int nt = 0; nt < 8; nt++) {
                    const int p = nt >> 1, o = (nt & 1) * 2;
                    mma_f32(accF[mt][nt], ah[mt], bh[p][o], bh[p][o + 1]);
                    mma_f16a(accC[mt][nt], ah[mt], bl[p][o], bl[p][o + 1]);
                }
            }
        }
    }

#pragma unroll
    for (int mt = 0; mt < 2; mt++) {
#pragma unroll
        for (int nt = 0; nt < 8; nt++) {
            float2 c0 = h2f2(accC[mt][nt][0]);
            float2 c1 = h2f2(accC[mt][nt][1]);
            int r = row0 + warpM * 32 + mt * 16 + (lane >> 2);
            int c = col0 + warpN * 64 + nt * 8 + (lane & 3) * 2;
            *(float2*)(C + (size_t)r * ldc + c) =
                make_float2(accF[mt][nt][0] + c0.x, accF[mt][nt][1] + c0.y);
            *(float2*)(C + (size_t)(r + 8) * ldc + c) =
                make_float2(accF[mt][nt][2] + c1.x, accF[mt][nt][3] + c1.y);
        }
    }
}

// ---------------------------------------------------------------------------
// RoPE (table) + fp16 convert/split + repack to head-major [B,H,S,64].
// q: hi only (A-side). k, v: hi + lo (B-side).
// ---------------------------------------------------------------------------
__global__ void rope_split_kernel(const float* __restrict__ qkv,
                                  const float* __restrict__ tbl,
                                  __half* __restrict__ qh,
                                  __half* __restrict__ kh, __half* __restrict__ kl,
                                  __half* __restrict__ vh, __half* __restrict__ vl) {
    int idx = blockIdx.x * blockDim.x + threadIdx.x;
    int lane16 = idx & 15;
    int row = idx >> 4;
    int s = row % SV;
    int r2 = row / SV;
    int bh = r2 % (BV * HV);
    int tt = r2 / (BV * HV);            // 0=q, 1=k, 2=v
    int b = bh / HV, h = bh % HV;

    const float* src = qkv + ((size_t)(b * SV + s)) * (3 * DV) + tt * DV + h * KD + lane16 * 4;
    float4 v = *(const float4*)src;

    if (tt < 2 && lane16 < 8) {
        // pairs i0 = 2*lane16, i0+1 ; table holds (sin, cos) contiguously
        float4 tc = *(const float4*)(tbl + (size_t)(s * 16 + lane16 * 2) * 2);
        float a  = v.x * tc.y - v.y * tc.x;
        float bq = v.y * tc.y + v.x * tc.x;
        float c  = v.z * tc.w - v.w * tc.z;
        float d  = v.w * tc.w + v.z * tc.z;
        v = make_float4(a, bq, c, d);
    }

    size_t o = ((size_t)bh * SV + s) * KD + lane16 * 4;
    __half2 h0 = __floats2half2_rn(v.x, v.y);
    __half2 h1 = __floats2half2_rn(v.z, v.w);

    if (tt == 0) {
        *(__half2*)(qh + o)     = h0;
        *(__half2*)(qh + o + 2) = h1;
        return;
    }
    __half* dh = (tt == 1) ? kh : vh;
    __half* dl = (tt == 1) ? kl : vl;
    __half2 l0 = __floats2half2_rn(v.x - __low2float(h0), v.y - __high2float(h0));
    __half2 l1 = __floats2half2_rn(v.z - __low2float(h1), v.w - __high2float(h1));
    *(__half2*)(dh + o)     = h0;
    *(__half2*)(dh + o + 2) = h1;
    *(__half2*)(dl + o)     = l0;
    *(__half2*)(dl + o + 2) = l1;
}

// ---------------------------------------------------------------------------
// Tensor-core causal flash attention.
// S = Qh*Kh (f32) + Qh*Kl (f16a);  Y = Ph*Vh (f32) + Ph*Vl (f16a).
// grid = (B*H, S/128) with qt reversed (longest CTAs first), 256 threads.
// SMEM: Qh (16KB) + 2-stage {Kh,Kl,Vh,Vl} (2x64KB) = 144KB.
// ---------------------------------------------------------------------------
#define FA_SMEM (16384 + 2 * 65536)

__device__ __forceinline__ void fa_load_kv(
    uint32_t base, const __half* kh, const __half* kl,
    const __half* vh, const __half* vl,
    int kt, int cm, int cc) {
    const __half* srcs[4] = { kh, kl, vh, vl };
#pragma unroll
    for (int tt = 0; tt < 4; tt++) {
#pragma unroll
        for (int j = 0; j < 4; j++) {
            int r = cm + 32 * j;
            cp16(base + tt * 16384 + SWZ(r * 128 + cc * 16),
                 srcs[tt] + (size_t)(kt * 128 + r) * KD + cc * 8);
        }
    }
    CP_COMMIT();
}

__global__ __launch_bounds__(256, 1)
void flash_mma(const __half* __restrict__ qh,
               const __half* __restrict__ kh, const __half* __restrict__ kl,
               const __half* __restrict__ vh, const __half* __restrict__ vl,
               __half* __restrict__ yhp) {
    extern __shared__ __align__(1024) char sm[];
    const uint32_t sb = smem_u32(sm);
    const int t = threadIdx.x, lane = t & 31, w = t >> 5;
    const int bh = blockIdx.x;
    const int qt = (int)gridDim.y - 1 - (int)blockIdx.y;   // longest first
    const size_t ho = (size_t)bh * SV * KD;

    const int cm = t >> 3, cc = t & 7;

    {
        const __half* qsrc = qh + ho + (size_t)qt * 128 * KD;
#pragma unroll
        for (int j = 0; j < 4; j++) {
            int r = cm + 32 * j;
            cp16(sb + SWZ(r * 128 + cc * 16), qsrc + (size_t)r * KD + cc * 8);
        }
        CP_COMMIT();
    }
    fa_load_kv(sb + 16384, kh + ho, kl + ho, vh + ho, vl + ho, 0, cm, cc);

    const int nt = qt + 1;
    const int sub = lane >> 3, l7 = lane & 7;

    uint32_t qfh[4][4];
    float m0 = -3.0e38f, m1 = -3.0e38f, l0 = 0.0f, l1 = 0.0f;
    float yacc[8][4];
#pragma unroll
    for (int p = 0; p < 8; p++)
#pragma unroll
        for (int e = 0; e < 4; e++) yacc[p][e] = 0.0f;

    for (int kt = 0; kt < nt; kt++) {
        const int st = kt & 1;
        CP_WAIT0();
        __syncthreads();

        if (kt == 0) {
            const int rA = w * 16 + ((sub & 1) << 3) + l7;
            const int kA = sub >> 1;
#pragma unroll
            for (int kc = 0; kc < 4; kc++)
                ldm4(qfh[kc], sb + SWZ(rA * 128 + (kc * 2 + kA) * 16));
        }
        if (kt + 1 < nt)
            fa_load_kv(sb + 16384 + (st ^ 1) * 65536,
                       kh + ho, kl + ho, vh + ho, vl + ho, kt + 1, cm, cc);

        const uint32_t KhB = sb + 16384 + st * 65536;
        const uint32_t KlB = KhB + 16384;
        const uint32_t VhB = KhB + 32768;
        const uint32_t VlB = KhB + 49152;

        // ---- S = Q K^T ----
        float sacc[16][4];
        uint32_t cacc[16][2];
#pragma unroll
        for (int n8 = 0; n8 < 16; n8++) {
#pragma unroll
            for (int e = 0; e < 4; e++) sacc[n8][e] = 0.0f;
            cacc[n8][0] = 0u; cacc[n8][1] = 0u;
        }

        const int rB = ((sub >> 1) << 3) + l7;
        const int kB = sub & 1;
#pragma unroll
        for (int kc = 0; kc < 4; kc++) {
#pragma unroll
            for (int p = 0; p < 8; p++) {
                uint32_t off = SWZ((p * 16 + rB) * 128 + (kc * 2 + kB) * 16);
                uint32_t kh4[4], kl4[4];
                ldm4(kh4, KhB + off);
                ldm4(kl4, KlB + off);
                mma_f32(sacc[2 * p], qfh[kc], kh4[0], kh4[1]);
                mma_f16a(cacc[2 * p], qfh[kc], kl4[0], kl4[1]);
                mma_f32(sacc[2 * p + 1], qfh[kc], kh4[2], kh4[3]);
                mma_f16a(cacc[2 * p + 1], qfh[kc], kl4[2], kl4[3]);
            }
        }
#pragma unroll
        for (int n8 = 0; n8 < 16; n8++) {
            float2 c0 = h2f2(cacc[n8][0]);
            float2 c1 = h2f2(cacc[n8][1]);
            sacc[n8][0] += c0.x; sacc[n8][1] += c0.y;
            sacc[n8][2] += c1.x; sacc[n8][3] += c1.y;
        }

        // causal mask on diagonal tile
        const int rr0 = w * 16 + (lane >> 2);
        if (kt == qt) {
#pragma unroll
            for (int n8 = 0; n8 < 16; n8++) {
                int cb = n8 * 8 + (lane & 3) * 2;
                if (cb     > rr0)     sacc[n8][0] = -1e30f;
                if (cb + 1 > rr0)     sacc[n8][1] = -1e30f;
                if (cb     > rr0 + 8) sacc[n8][2] = -1e30f;
                if (cb + 1 > rr0 + 8) sacc[n8][3] = -1e30f;
            }
        }

        // ---- online softmax ----
        float mx0 = -3.0e38f, mx1 = -3.0e38f;
#pragma unroll
        for (int n8 = 0; n8 < 16; n8++) {
            mx0 = fmaxf(mx0, fmaxf(sacc[n8][0], sacc[n8][1]));
            mx1 = fmaxf(mx1, fmaxf(sacc[n8][2], sacc[n8][3]));
        }
        mx0 = fmaxf(mx0, __shfl_xor_sync(0xffffffffu, mx0, 1));
        mx0 = fmaxf(mx0, __shfl_xor_sync(0xffffffffu, mx0, 2));
        mx1 = fmaxf(mx1, __shfl_xor_sync(0xffffffffu, mx1, 1));
        mx1 = fmaxf(mx1, __shfl_xor_sync(0xffffffffu, mx1, 2));
        const float mt0 = fmaxf(m0, mx0), mt1 = fmaxf(m1, mx1);
        const float sc0 = __expf(m0 - mt0), sc1 = __expf(m1 - mt1);
        l0 *= sc0; l1 *= sc1;
#pragma unroll
        for (int p = 0; p < 8; p++) {
            yacc[p][0] *= sc0; yacc[p][1] *= sc0;
            yacc[p][2] *= sc1; yacc[p][3] *= sc1;
        }
        m0 = mt0; m1 = mt1;

        // p = exp(s - m) -> fp16 A-fragments (hi only)
        uint32_t aH[8][4];
        float rs0 = 0.0f, rs1 = 0.0f;
#pragma unroll
        for (int kc = 0; kc < 8; kc++) {
#pragma unroll
            for (int e = 0; e < 2; e++) {
                const int n8 = 2 * kc + e;
                float p0 = __expf(sacc[n8][0] - mt0);
                float p1 = __expf(sacc[n8][1] - mt0);
                float p2 = __expf(sacc[n8][2] - mt1);
                float p3 = __expf(sacc[n8][3] - mt1);
                rs0 += p0 + p1; rs1 += p2 + p3;
                aH[kc][2 * e]     = b2u(__floats2half2_rn(p0, p1));
                aH[kc][2 * e + 1] = b2u(__floats2half2_rn(p2, p3));
            }
        }
        rs0 += __shfl_xor_sync(0xffffffffu, rs0, 1);
        rs0 += __shfl_xor_sync(0xffffffffu, rs0, 2);
        rs1 += __shfl_xor_sync(0xffffffffu, rs1, 1);
        rs1 += __shfl_xor_sync(0xffffffffu, rs1, 2);
        l0 += rs0; l1 += rs1;

        // ---- Y += P V ----
        uint32_t ycc[8][2];
#pragma unroll
        for (int p = 0; p < 8; p++) { ycc[p][0] = 0u; ycc[p][1] = 0u; }

        const int vr = ((lane >> 3) & 1) * 8 + (lane & 7);
        const int vc = (lane >> 4) * 8;
#pragma unroll
        for (int kc = 0; kc < 8; kc++) {
#pragma unroll
            for (int p = 0; p < 4; p++) {
                uint32_t off = SWZ((kc * 16 + vr) * 128 + (p * 16 + vc) * 2);
                uint32_t vh4[4], vl4[4];
                ldm4t(vh4, VhB + off);
                ldm4t(vl4, VlB + off);
                mma_f32(yacc[2 * p], aH[kc], vh4[0], vh4[1]);
                mma_f16a(ycc[2 * p], aH[kc], vl4[0], vl4[1]);
                mma_f32(yacc[2 * p + 1], aH[kc], vh4[2], vh4[3]);
                mma_f16a(ycc[2 * p + 1], aH[kc], vl4[2], vl4[3]);
            }
        }
#pragma unroll
        for (int p = 0; p < 8; p++) {
            float2 c0 = h2f2(ycc[p][0]);
            float2 c1 = h2f2(ycc[p][1]);
            yacc[p][0] += c0.x; yacc[p][1] += c0.y;
            yacc[p][2] += c1.x; yacc[p][3] += c1.y;
        }
        __syncthreads();
    }

    // epilogue: normalize, fp16 convert, write [B,S,D]
    const float il0 = 1.0f / l0, il1 = 1.0f / l1;
    const int b = bh / HV, h = bh % HV;
    const int gr0 = qt * 128 + w * 16 + (lane >> 2);
    const size_t o0 = ((size_t)(b * SV) + gr0) * DV + h * KD;
    const size_t o1 = o0 + (size_t)8 * DV;
#pragma unroll
    for (int p = 0; p < 8; p++) {
        int c = p * 8 + (lane & 3) * 2;
        *(__half2*)(yhp + o0 + c) = __floats2half2_rn(yacc[p][0] * il0, yacc[p][1] * il0);
        *(__half2*)(yhp + o1 + c) = __floats2half2_rn(yacc[p][2] * il1, yacc[p][3] * il1);
    }
}

// ---------------------------------------------------------------------------
// kernel_launch
// ---------------------------------------------------------------------------
extern "C" void kernel_launch(void* const* d_in, const int* in_sizes, int n_in,
                              void* d_out, int out_size) {
    (void)in_sizes; (void)n_in; (void)out_size;
    const float* x  = (const float*)d_in[0];
    const float* Wq = (const float*)d_in[2];
    const float* Wk = (const float*)d_in[3];
    const float* Wv = (const float*)d_in[4];
    const float* Wo = (const float*)d_in[5];
    float* out = (float*)d_out;

    float *qkv, *tbl;
    __half *xh, *wh, *wl, *qh, *kh, *kl, *vh, *vl, *yh;
    cudaGetSymbolAddress((void**)&qkv, g_qkv);
    cudaGetSymbolAddress((void**)&tbl, g_rope);
    cudaGetSymbolAddress((void**)&xh, g_xh);
    cudaGetSymbolAddress((void**)&wh, g_wh);
    cudaGetSymbolAddress((void**)&wl, g_wl);
    cudaGetSymbolAddress((void**)&qh, g_qh);
    cudaGetSymbolAddress((void**)&kh, g_kh);
    cudaGetSymbolAddress((void**)&kl, g_kl);
    cudaGetSymbolAddress((void**)&vh, g_vh);
    cudaGetSymbolAddress((void**)&vl, g_vl);
    cudaGetSymbolAddress((void**)&yh, g_yh);

    cudaFuncSetAttribute(mma_gemm, cudaFuncAttributeMaxDynamicSharedMemorySize, GEMM_SMEM);
    cudaFuncSetAttribute(flash_mma, cudaFuncAttributeMaxDynamicSharedMemorySize, FA_SMEM);

    int n4 = MROWS * DV / 4;
    tohalf_kernel<<<(n4 + 255) / 256, 256>>>(x, xh, n4);

    dim3 tgrid(DV / 32, DV / 32, 4);
    dim3 tblk(32, 8);
    trans_split4_kernel<<<tgrid, tblk>>>(Wq, Wk, Wv, Wo, wh, wl);

    rope_table_kernel<<<(SV * 16 + 255) / 256, 256>>>(tbl);

    // fused QKV projection: N = 3072
    dim3 qkvgrid(3 * DV / GBN, MROWS / GBM);   // (24, 32)
    mma_gemm<<<qkvgrid, 256, GEMM_SMEM>>>(xh, wh, wl, qkv, 3 * DV);

    // rope + split + head-major repack
    int rthreads = 3 * BV * HV * SV * 16;
    rope_split_kernel<<<rthreads / 256, 256>>>(qkv, tbl, qh, kh, kl, vh, vl);

    // tensor-core flash attention (longest CTAs scheduled first)
    dim3 fgrid(BV * HV, SV / 128);             // (32, 16)
    flash_mma<<<fgrid, 256, FA_SMEM>>>(qh, kh, kl, vh, vl, yh);

    // output projection
    dim3 ogrid(DV / GBN, MROWS / GBM);         // (8, 32)
    mma_gemm<<<ogrid, 256, GEMM_SMEM>>>(yh, wh + 3 * (size_t)DV * DV,
                                        wl + 3 * (size_t)DV * DV, out, DV);
}

// round 7
// speedup vs baseline: 5.7135x; 1.0030x over previous
#include <cuda_runtime.h>
#include <cuda_fp16.h>
#include <math.h>
#include <stdint.h>
#include <string.h>

// ---------------------------------------------------------------------------
// Problem constants: B=2, S=2048, D=1024, H=16, head_dim=64, rope dims=32
// ---------------------------------------------------------------------------
#define BV 2
#define HV 16
#define SV 2048
#define DV 1024
#define KD 64
#define MROWS (BV*SV)        // 4096
#define HEADROWS (BV*HV*SV)  // 65536

// Scratch (device globals: allocation-free rule)
__device__ float g_rope[SV * 16 * 2];     // (sin, cos) per (s, pair)
__device__ __half g_xh[MROWS * DV];
__device__ __half g_wh[4 * DV * DV];
__device__ __half g_wl[4 * DV * DV];
__device__ __half g_qh[HEADROWS * KD];
__device__ __half g_kh[HEADROWS * KD];
__device__ __half g_kl[HEADROWS * KD];
__device__ __half g_vh[HEADROWS * KD];
__device__ __half g_vl[HEADROWS * KD];
__device__ __half g_yh[MROWS * DV];

// ---------------------------------------------------------------------------
// helpers
// ---------------------------------------------------------------------------
__device__ __forceinline__ uint32_t smem_u32(const void* p) {
    uint32_t a;
    asm("{ .reg .u64 t; cvta.to.shared.u64 t, %1; cvt.u32.u64 %0, t; }"
        : "=r"(a) : "l"(p));
    return a;
}

#define SWZ(o) ((o) ^ (((o) >> 3) & 0x70))

__device__ __forceinline__ void ldm4(uint32_t* r, uint32_t addr) {
    asm volatile("ldmatrix.sync.aligned.m8n8.x4.shared.b16 {%0,%1,%2,%3}, [%4];"
                 : "=r"(r[0]), "=r"(r[1]), "=r"(r[2]), "=r"(r[3]) : "r"(addr));
}

__device__ __forceinline__ void ldm4t(uint32_t* r, uint32_t addr) {
    asm volatile("ldmatrix.sync.aligned.m8n8.x4.trans.shared.b16 {%0,%1,%2,%3}, [%4];"
                 : "=r"(r[0]), "=r"(r[1]), "=r"(r[2]), "=r"(r[3]) : "r"(addr));
}

// f32-accumulate fp16 mma (main hi*hi pass)
__device__ __forceinline__ void mma_f32(float* c, const uint32_t* a,
                                        uint32_t b0, uint32_t b1) {
    asm volatile(
        "mma.sync.aligned.m16n8k16.row.col.f32.f16.f16.f32 "
        "{%0,%1,%2,%3},{%4,%5,%6,%7},{%8,%9},{%0,%1,%2,%3};"
        : "+f"(c[0]), "+f"(c[1]), "+f"(c[2]), "+f"(c[3])
        : "r"(a[0]), "r"(a[1]), "r"(a[2]), "r"(a[3]), "r"(b0), "r"(b1));
}

// f16-accumulate fp16 mma (correction pass, 2x rate)
__device__ __forceinline__ void mma_f16a(uint32_t* c, const uint32_t* a,
                                         uint32_t b0, uint32_t b1) {
    asm volatile(
        "mma.sync.aligned.m16n8k16.row.col.f16.f16.f16.f16 "
        "{%0,%1},{%2,%3,%4,%5},{%6,%7},{%0,%1};"
        : "+r"(c[0]), "+r"(c[1])
        : "r"(a[0]), "r"(a[1]), "r"(a[2]), "r"(a[3]), "r"(b0), "r"(b1));
}

__device__ __forceinline__ void cp16(uint32_t saddr, const void* gaddr) {
    asm volatile("cp.async.cg.shared.global [%0], [%1], 16;"
                 :: "r"(saddr), "l"(gaddr) : "memory");
}
#define CP_COMMIT() asm volatile("cp.async.commit_group;" ::: "memory")
#define CP_WAIT1()  asm volatile("cp.async.wait_group 1;" ::: "memory")
#define CP_WAIT0()  asm volatile("cp.async.wait_group 0;" ::: "memory")

__device__ __forceinline__ uint32_t b2u(__half2 v) {
    uint32_t u;
    memcpy(&u, &v, 4);
    return u;
}

__device__ __forceinline__ float2 h2f2(uint32_t u) {
    __half2 h;
    memcpy(&h, &u, 4);
    return __half22float2(h);
}

// ---------------------------------------------------------------------------
// fp32 -> fp16 convert of x (A-side hi only)
// ---------------------------------------------------------------------------
__global__ void tohalf_kernel(const float* __restrict__ src,
                              __half* __restrict__ hi, int n4) {
    int i = blockIdx.x * blockDim.x + threadIdx.x;
    if (i >= n4) return;
    float4 v = ((const float4*)src)[i];
    *(__half2*)(hi + 4 * i)     = __floats2half2_rn(v.x, v.y);
    *(__half2*)(hi + 4 * i + 2) = __floats2half2_rn(v.z, v.w);
}

// ---------------------------------------------------------------------------
// RoPE sin/cos table (same powf/sincosf math as verified inline version)
// ---------------------------------------------------------------------------
__global__ void rope_table_kernel(float* __restrict__ tbl) {
    int idx = blockIdx.x * blockDim.x + threadIdx.x;
    if (idx >= SV * 16) return;
    int i = idx & 15, s = idx >> 4;
    float inv = powf(10000.0f, -(float)i / 16.0f);
    float sn, cs;
    sincosf((float)s * inv, &sn, &cs);
    tbl[2 * idx]     = sn;
    tbl[2 * idx + 1] = cs;
}

// ---------------------------------------------------------------------------
// Fused weight transpose + scale + split for all 4 weights (blockIdx.z picks)
// ---------------------------------------------------------------------------
__global__ void trans_split4_kernel(const float* __restrict__ W0,
                                    const float* __restrict__ W1,
                                    const float* __restrict__ W2,
                                    const float* __restrict__ W3,
                                    __half* __restrict__ hi_all,
                                    __half* __restrict__ lo_all) {
    __shared__ float tile[32][33];
    const float* Ws[4] = { W0, W1, W2, W3 };
    const float* W = Ws[blockIdx.z];
    const float scale = (blockIdx.z == 0) ? 0.125f : 1.0f;
    __half* hi = hi_all + (size_t)blockIdx.z * DV * DV;
    __half* lo = lo_all + (size_t)blockIdx.z * DV * DV;

    int bx = blockIdx.x * 32, by = blockIdx.y * 32;
    int tx = threadIdx.x, ty = threadIdx.y;
#pragma unroll
    for (int r = 0; r < 32; r += 8)
        tile[ty + r][tx] = W[(size_t)(by + ty + r) * DV + bx + tx];
    __syncthreads();
#pragma unroll
    for (int r = 0; r < 32; r += 8) {
        float v = tile[tx][ty + r] * scale;
        __half h = __float2half_rn(v);
        size_t o = (size_t)(bx + ty + r) * DV + by + tx;
        hi[o] = h;
        lo[o] = __float2half_rn(v - __half2float(h));
    }
}

// ---------------------------------------------------------------------------
// fp16x2 emulated GEMM: C = Ah @ (Bh + Bl)^T.
// 128x128 block tile, BK=64, cp.async double buffer, 512 threads (16 warps,
// 4x4 layout, 32x32 warp tile).
// MODE 0: plain fp32 C output.
// MODE 1: fused QKV epilogue — RoPE (table) + fp16 hi(/lo) split + head-major
//         repack straight from accumulators (no fp32 qkv round-trip).
// ---------------------------------------------------------------------------
#define GBM 128
#define GBN 128
#define GBK 64
#define TILE_BYTES (GBM * GBK * 2)
#define STAGE_BYTES (3 * TILE_BYTES)      // Ah, Bh, Bl
#define GEMM_SMEM (2 * STAGE_BYTES)       // 98304
#define NITER (DV / GBK)

__device__ __forceinline__ void qkv_store(
    int r, int c, float v0, float v1, const float* __restrict__ tbl,
    __half* __restrict__ qh,
    __half* __restrict__ kh, __half* __restrict__ kl,
    __half* __restrict__ vh, __half* __restrict__ vl) {
    const int b = r >> 11, s = r & (SV - 1);
    const int tt = c >> 10;              // 0=q, 1=k, 2=v
    const int cd = c & (DV - 1);
    const int h = cd >> 6, d = cd & (KD - 1);
    if (tt < 2 && d < 32) {
        float2 sc = *(const float2*)(tbl + (size_t)(s * 16 + (d >> 1)) * 2);
        float a = v0 * sc.y - v1 * sc.x;
        float bq = v1 * sc.y + v0 * sc.x;
        v0 = a; v1 = bq;
    }
    const size_t o = (((size_t)(b * HV + h)) * SV + s) * KD + d;
    __half2 hi = __floats2half2_rn(v0, v1);
    if (tt == 0) {
        *(__half2*)(qh + o) = hi;
        return;
    }
    __half2 lo = __floats2half2_rn(v0 - __low2float(hi), v1 - __high2float(hi));
    if (tt == 1) {
        *(__half2*)(kh + o) = hi;
        *(__half2*)(kl + o) = lo;
    } else {
        *(__half2*)(vh + o) = hi;
        *(__half2*)(vl + o) = lo;
    }
}

template <int MODE>
__global__ __launch_bounds__(512, 1)
void mma_gemm(const __half* __restrict__ Ah,
              const __half* __restrict__ Bh,
              const __half* __restrict__ Bl,
              float* __restrict__ C, int ldc,
              const float* __restrict__ tbl,
              __half* __restrict__ qh,
              __half* __restrict__ kh, __half* __restrict__ kl,
              __half* __restrict__ vh, __half* __restrict__ vl) {
    extern __shared__ __align__(1024) char sm[];
    const uint32_t sb = smem_u32(sm);
    const int t = threadIdx.x;
    const int lane = t & 31, wid = t >> 5;
    const int warpM = wid & 3, warpN = wid >> 2;
    const int row0 = blockIdx.y * GBM;
    const int col0 = blockIdx.x * GBN;

    const __half* srcs[3] = {
        Ah + (size_t)row0 * DV,
        Bh + (size_t)col0 * DV, Bl + (size_t)col0 * DV };

    const int cm = t >> 3;        // 0..63
    const int cc = t & 7;

    float accF[2][4][4];
    uint32_t accC[2][4][2];
#pragma unroll
    for (int i = 0; i < 2; i++)
#pragma unroll
        for (int j = 0; j < 4; j++) {
#pragma unroll
            for (int r = 0; r < 4; r++) accF[i][j][r] = 0.0f;
            accC[i][j][0] = 0u; accC[i][j][1] = 0u;
        }

    const int sub = lane >> 3, l7 = lane & 7;
    const int rowA0 = warpM * 32 + ((sub & 1) << 3) + l7;
    const int rowA1 = rowA0 + 16;
    const int kA = (sub >> 1);
    int rowB[2];
#pragma unroll
    for (int p = 0; p < 2; p++)
        rowB[p] = warpN * 32 + p * 16 + ((sub >> 1) << 3) + l7;
    const int kB = (sub & 1);

    {
#pragma unroll
        for (int tile = 0; tile < 3; tile++) {
#pragma unroll
            for (int j = 0; j < 2; j++) {
                int m = cm + 64 * j;
                cp16(sb + tile * TILE_BYTES + SWZ(m * 128 + cc * 16),
                     srcs[tile] + (size_t)m * DV + cc * 8);
            }
        }
        CP_COMMIT();
    }

    for (int it = 0; it < NITER; it++) {
        const int buf = it & 1;
        __syncthreads();
        if (it + 1 < NITER) {
            const int k0 = (it + 1) * GBK;
            const uint32_t stb = sb + ((it + 1) & 1) * STAGE_BYTES;
#pragma unroll
            for (int tile = 0; tile < 3; tile++) {
#pragma unroll
                for (int j = 0; j < 2; j++) {
                    int m = cm + 64 * j;
                    cp16(stb + tile * TILE_BYTES + SWZ(m * 128 + cc * 16),
                         srcs[tile] + (size_t)m * DV + k0 + cc * 8);
                }
            }
            CP_COMMIT();
            CP_WAIT1();
        } else {
            CP_WAIT0();
        }
        __syncthreads();

        const uint32_t ahB = sb + buf * STAGE_BYTES;
        const uint32_t bhB = ahB + TILE_BYTES;
        const uint32_t blB = ahB + 2 * TILE_BYTES;

#pragma unroll
        for (int ks = 0; ks < 4; ks++) {
            const int kcA = ks * 2 + kA;
            const int kcB = ks * 2 + kB;
            uint32_t ah[2][4];
            ldm4(ah[0], ahB + SWZ(rowA0 * 128 + kcA * 16));
            ldm4(ah[1], ahB + SWZ(rowA1 * 128 + kcA * 16));
            uint32_t bh[2][4], bl[2][4];
#pragma unroll
            for (int p = 0; p < 2; p++) {
                ldm4(bh[p], bhB + SWZ(rowB[p] * 128 + kcB * 16));
                ldm4(bl[p], blB + SWZ(rowB[p] * 128 + kcB * 16));
            }
#pragma unroll
            for (int mt = 0; mt < 2; mt++) {
#pragma unroll
                for (int nt = 0; nt < 4; nt++) {
                    const int p = nt >> 1, o = (nt & 1) * 2;
                    mma_f32(accF[mt][nt], ah[mt], bh[p][o], bh[p][o + 1]);
                    mma_f16a(accC[mt][nt], ah[mt], bl[p][o], bl[p][o + 1]);
                }
            }
        }
    }

#pragma unroll
    for (int mt = 0; mt < 2; mt++) {
#pragma unroll
        for (int nt = 0; nt < 4; nt++) {
            float2 c0 = h2f2(accC[mt][nt][0]);
            float2 c1 = h2f2(accC[mt][nt][1]);
            float v0 = accF[mt][nt][0] + c0.x, v1 = accF[mt][nt][1] + c0.y;
            float v2 = accF[mt][nt][2] + c1.x, v3 = accF[mt][nt][3] + c1.y;
            int r = row0 + warpM * 32 + mt * 16 + (lane >> 2);
            int c = col0 + warpN * 32 + nt * 8 + (lane & 3) * 2;
            if (MODE == 0) {
                *(float2*)(C + (size_t)r * ldc + c) = make_float2(v0, v1);
                *(float2*)(C + (size_t)(r + 8) * ldc + c) = make_float2(v2, v3);
            } else {
                qkv_store(r, c, v0, v1, tbl, qh, kh, kl, vh, vl);
                qkv_store(r + 8, c, v2, v3, tbl, qh, kh, kl, vh, vl);
            }
        }
    }
}

// ---------------------------------------------------------------------------
// Tensor-core causal flash attention (unchanged from round 6).
// S = Qh*Kh (f32) + Qh*Kl (f16a);  Y = Ph*Vh (f32) + Ph*Vl (f16a).
// grid = (B*H, S/128) with qt reversed (longest CTAs first), 256 threads.
// ---------------------------------------------------------------------------
#define FA_SMEM (16384 + 2 * 65536)

__device__ __forceinline__ void fa_load_kv(
    uint32_t base, const __half* kh, const __half* kl,
    const __half* vh, const __half* vl,
    int kt, int cm, int cc) {
    const __half* srcs[4] = { kh, kl, vh, vl };
#pragma unroll
    for (int tt = 0; tt < 4; tt++) {
#pragma unroll
        for (int j = 0; j < 4; j++) {
            int r = cm + 32 * j;
            cp16(base + tt * 16384 + SWZ(r * 128 + cc * 16),
                 srcs[tt] + (size_t)(kt * 128 + r) * KD + cc * 8);
        }
    }
    CP_COMMIT();
}

__global__ __launch_bounds__(256, 1)
void flash_mma(const __half* __restrict__ qh,
               const __half* __restrict__ kh, const __half* __restrict__ kl,
               const __half* __restrict__ vh, const __half* __restrict__ vl,
               __half* __restrict__ yhp) {
    extern __shared__ __align__(1024) char sm[];
    const uint32_t sb = smem_u32(sm);
    const int t = threadIdx.x, lane = t & 31, w = t >> 5;
    const int bh = blockIdx.x;
    const int qt = (int)gridDim.y - 1 - (int)blockIdx.y;   // longest first
    const size_t ho = (size_t)bh * SV * KD;

    const int cm = t >> 3, cc = t & 7;

    {
        const __half* qsrc = qh + ho + (size_t)qt * 128 * KD;
#pragma unroll
        for (int j = 0; j < 4; j++) {
            int r = cm + 32 * j;
            cp16(sb + SWZ(r * 128 + cc * 16), qsrc + (size_t)r * KD + cc * 8);
        }
        CP_COMMIT();
    }
    fa_load_kv(sb + 16384, kh + ho, kl + ho, vh + ho, vl + ho, 0, cm, cc);

    const int nt = qt + 1;
    const int sub = lane >> 3, l7 = lane & 7;

    uint32_t qfh[4][4];
    float m0 = -3.0e38f, m1 = -3.0e38f, l0 = 0.0f, l1 = 0.0f;
    float yacc[8][4];
#pragma unroll
    for (int p = 0; p < 8; p++)
#pragma unroll
        for (int e = 0; e < 4; e++) yacc[p][e] = 0.0f;

    for (int kt = 0; kt < nt; kt++) {
        const int st = kt & 1;
        CP_WAIT0();
        __syncthreads();

        if (kt == 0) {
            const int rA = w * 16 + ((sub & 1) << 3) + l7;
            const int kA = sub >> 1;
#pragma unroll
            for (int kc = 0; kc < 4; kc++)
                ldm4(qfh[kc], sb + SWZ(rA * 128 + (kc * 2 + kA) * 16));
        }
        if (kt + 1 < nt)
            fa_load_kv(sb + 16384 + (st ^ 1) * 65536,
                       kh + ho, kl + ho, vh + ho, vl + ho, kt + 1, cm, cc);

        const uint32_t KhB = sb + 16384 + st * 65536;
        const uint32_t KlB = KhB + 16384;
        const uint32_t VhB = KhB + 32768;
        const uint32_t VlB = KhB + 49152;

        // ---- S = Q K^T ----
        float sacc[16][4];
        uint32_t cacc[16][2];
#pragma unroll
        for (int n8 = 0; n8 < 16; n8++) {
#pragma unroll
            for (int e = 0; e < 4; e++) sacc[n8][e] = 0.0f;
            cacc[n8][0] = 0u; cacc[n8][1] = 0u;
        }

        const int rB = ((sub >> 1) << 3) + l7;
        const int kB = sub & 1;
#pragma unroll
        for (int kc = 0; kc < 4; kc++) {
#pragma unroll
            for (int p = 0; p < 8; p++) {
                uint32_t off = SWZ((p * 16 + rB) * 128 + (kc * 2 + kB) * 16);
                uint32_t kh4[4], kl4[4];
                ldm4(kh4, KhB + off);
                ldm4(kl4, KlB + off);
                mma_f32(sacc[2 * p], qfh[kc], kh4[0], kh4[1]);
                mma_f16a(cacc[2 * p], qfh[kc], kl4[0], kl4[1]);
                mma_f32(sacc[2 * p + 1], qfh[kc], kh4[2], kh4[3]);
                mma_f16a(cacc[2 * p + 1], qfh[kc], kl4[2], kl4[3]);
            }
        }
#pragma unroll
        for (int n8 = 0; n8 < 16; n8++) {
            float2 c0 = h2f2(cacc[n8][0]);
            float2 c1 = h2f2(cacc[n8][1]);
            sacc[n8][0] += c0.x; sacc[n8][1] += c0.y;
            sacc[n8][2] += c1.x; sacc[n8][3] += c1.y;
        }

        // causal mask on diagonal tile
        const int rr0 = w * 16 + (lane >> 2);
        if (kt == qt) {
#pragma unroll
            for (int n8 = 0; n8 < 16; n8++) {
                int cb = n8 * 8 + (lane & 3) * 2;
                if (cb     > rr0)     sacc[n8][0] = -1e30f;
                if (cb + 1 > rr0)     sacc[n8][1] = -1e30f;
                if (cb     > rr0 + 8) sacc[n8][2] = -1e30f;
                if (cb + 1 > rr0 + 8) sacc[n8][3] = -1e30f;
            }
        }

        // ---- online softmax ----
        float mx0 = -3.0e38f, mx1 = -3.0e38f;
#pragma unroll
        for (int n8 = 0; n8 < 16; n8++) {
            mx0 = fmaxf(mx0, fmaxf(sacc[n8][0], sacc[n8][1]));
            mx1 = fmaxf(mx1, fmaxf(sacc[n8][2], sacc[n8][3]));
        }
        mx0 = fmaxf(mx0, __shfl_xor_sync(0xffffffffu, mx0, 1));
        mx0 = fmaxf(mx0, __shfl_xor_sync(0xffffffffu, mx0, 2));
        mx1 = fmaxf(mx1, __shfl_xor_sync(0xffffffffu, mx1, 1));
        mx1 = fmaxf(mx1, __shfl_xor_sync(0xffffffffu, mx1, 2));
        const float mt0 = fmaxf(m0, mx0), mt1 = fmaxf(m1, mx1);
        const float sc0 = __expf(m0 - mt0), sc1 = __expf(m1 - mt1);
        l0 *= sc0; l1 *= sc1;
#pragma unroll
        for (int p = 0; p < 8; p++) {
            yacc[p][0] *= sc0; yacc[p][1] *= sc0;
            yacc[p][2] *= sc1; yacc[p][3] *= sc1;
        }
        m0 = mt0; m1 = mt1;

        // p = exp(s - m) -> fp16 A-fragments (hi only)
        uint32_t aH[8][4];
        float rs0 = 0.0f, rs1 = 0.0f;
#pragma unroll
        for (int kc = 0; kc < 8; kc++) {
#pragma unroll
            for (int e = 0; e < 2; e++) {
                const int n8 = 2 * kc + e;
                float p0 = __expf(sacc[n8][0] - mt0);
                float p1 = __expf(sacc[n8][1] - mt0);
                float p2 = __expf(sacc[n8][2] - mt1);
                float p3 = __expf(sacc[n8][3] - mt1);
                rs0 += p0 + p1; rs1 += p2 + p3;
                aH[kc][2 * e]     = b2u(__floats2half2_rn(p0, p1));
                aH[kc][2 * e + 1] = b2u(__floats2half2_rn(p2, p3));
            }
        }
        rs0 += __shfl_xor_sync(0xffffffffu, rs0, 1);
        rs0 += __shfl_xor_sync(0xffffffffu, rs0, 2);
        rs1 += __shfl_xor_sync(0xffffffffu, rs1, 1);
        rs1 += __shfl_xor_sync(0xffffffffu, rs1, 2);
        l0 += rs0; l1 += rs1;

        // ---- Y += P V ----
        uint32_t ycc[8][2];
#pragma unroll
        for (int p = 0; p < 8; p++) { ycc[p][0] = 0u; ycc[p][1] = 0u; }

        const int vr = ((lane >> 3) & 1) * 8 + (lane & 7);
        const int vc = (lane >> 4) * 8;
#pragma unroll
        for (int kc = 0; kc < 8; kc++) {
#pragma unroll
            for (int p = 0; p < 4; p++) {
                uint32_t off = SWZ((kc * 16 + vr) * 128 + (p * 16 + vc) * 2);
                uint32_t vh4[4], vl4[4];
                ldm4t(vh4, VhB + off);
                ldm4t(vl4, VlB + off);
                mma_f32(yacc[2 * p], aH[kc], vh4[0], vh4[1]);
                mma_f16a(ycc[2 * p], aH[kc], vl4[0], vl4[1]);
                mma_f32(yacc[2 * p + 1], aH[kc], vh4[2], vh4[3]);
                mma_f16a(ycc[2 * p + 1], aH[kc], vl4[2], vl4[3]);
            }
        }
#pragma unroll
        for (int p = 0; p < 8; p++) {
            float2 c0 = h2f2(ycc[p][0]);
            float2 c1 = h2f2(ycc[p][1]);
            yacc[p][0] += c0.x; yacc[p][1] += c0.y;
            yacc[p][2] += c1.x; yacc[p][3] += c1.y;
        }
        __syncthreads();
    }

    // epilogue: normalize, fp16 convert, write [B,S,D]
    const float il0 = 1.0f / l0, il1 = 1.0f / l1;
    const int b = bh / HV, h = bh % HV;
    const int gr0 = qt * 128 + w * 16 + (lane >> 2);
    const size_t o0 = ((size_t)(b * SV) + gr0) * DV + h * KD;
    const size_t o1 = o0 + (size_t)8 * DV;
#pragma unroll
    for (int p = 0; p < 8; p++) {
        int c = p * 8 + (lane & 3) * 2;
        *(__half2*)(yhp + o0 + c) = __floats2half2_rn(yacc[p][0] * il0, yacc[p][1] * il0);
        *(__half2*)(yhp + o1 + c) = __floats2half2_rn(yacc[p][2] * il1, yacc[p][3] * il1);
    }
}

// ---------------------------------------------------------------------------
// kernel_launch
// ---------------------------------------------------------------------------
extern "C" void kernel_launch(void* const* d_in, const int* in_sizes, int n_in,
                              void* d_out, int out_size) {
    (void)in_sizes; (void)n_in; (void)out_size;
    const float* x  = (const float*)d_in[0];
    const float* Wq = (const float*)d_in[2];
    const float* Wk = (const float*)d_in[3];
    const float* Wv = (const float*)d_in[4];
    const float* Wo = (const float*)d_in[5];
    float* out = (float*)d_out;

    float* tbl;
    __half *xh, *wh, *wl, *qh, *kh, *kl, *vh, *vl, *yh;
    cudaGetSymbolAddress((void**)&tbl, g_rope);
    cudaGetSymbolAddress((void**)&xh, g_xh);
    cudaGetSymbolAddress((void**)&wh, g_wh);
    cudaGetSymbolAddress((void**)&wl, g_wl);
    cudaGetSymbolAddress((void**)&qh, g_qh);
    cudaGetSymbolAddress((void**)&kh, g_kh);
    cudaGetSymbolAddress((void**)&kl, g_kl);
    cudaGetSymbolAddress((void**)&vh, g_vh);
    cudaGetSymbolAddress((void**)&vl, g_vl);
    cudaGetSymbolAddress((void**)&yh, g_yh);

    cudaFuncSetAttribute(mma_gemm<0>, cudaFuncAttributeMaxDynamicSharedMemorySize, GEMM_SMEM);
    cudaFuncSetAttribute(mma_gemm<1>, cudaFuncAttributeMaxDynamicSharedMemorySize, GEMM_SMEM);
    cudaFuncSetAttribute(flash_mma, cudaFuncAttributeMaxDynamicSharedMemorySize, FA_SMEM);

    int n4 = MROWS * DV / 4;
    tohalf_kernel<<<(n4 + 255) / 256, 256>>>(x, xh, n4);

    dim3 tgrid(DV / 32, DV / 32, 4);
    dim3 tblk(32, 8);
    trans_split4_kernel<<<tgrid, tblk>>>(Wq, Wk, Wv, Wo, wh, wl);

    rope_table_kernel<<<(SV * 16 + 255) / 256, 256>>>(tbl);

    // fused QKV projection (N = 3072) with fused rope/split/repack epilogue
    dim3 qkvgrid(3 * DV / GBN, MROWS / GBM);   // (24, 32)
    mma_gemm<1><<<qkvgrid, 512, GEMM_SMEM>>>(xh, wh, wl, nullptr, 0,
                                             tbl, qh, kh, kl, vh, vl);

    // tensor-core flash attention (longest CTAs scheduled first)
    dim3 fgrid(BV * HV, SV / 128);             // (32, 16)
    flash_mma<<<fgrid, 256, FA_SMEM>>>(qh, kh, kl, vh, vl, yh);

    // output projection
    dim3 ogrid(DV / GBN, MROWS / GBM);         // (8, 32)
    mma_gemm<0><<<ogrid, 512, GEMM_SMEM>>>(yh, wh + 3 * (size_t)DV * DV,
                                           wl + 3 * (size_t)DV * DV, out, DV,
                                           nullptr, nullptr, nullptr, nullptr,
                                           nullptr, nullptr);
}

// round 8
// speedup vs baseline: 5.7634x; 1.0087x over previous
#include <cuda_runtime.h>
#include <cuda_fp16.h>
#include <math.h>
#include <stdint.h>
#include <string.h>

// ---------------------------------------------------------------------------
// Problem constants: B=2, S=2048, D=1024, H=16, head_dim=64, rope dims=32
// ---------------------------------------------------------------------------
#define BV 2
#define HV 16
#define SV 2048
#define DV 1024
#define KD 64
#define MROWS (BV*SV)        // 4096
#define HEADROWS (BV*HV*SV)  // 65536

// Scratch (device globals: allocation-free rule)
__device__ float g_rope[SV * 16 * 2];     // (sin, cos) per (s, pair)
__device__ __half g_xh[MROWS * DV];
__device__ __half g_wh[4 * DV * DV];
__device__ __half g_wl[4 * DV * DV];
__device__ __half g_qh[HEADROWS * KD];
__device__ __half g_kh[HEADROWS * KD];
__device__ __half g_kl[HEADROWS * KD];
__device__ __half g_vh[HEADROWS * KD];
__device__ __half g_vl[HEADROWS * KD];
__device__ __half g_yh[MROWS * DV];

// ---------------------------------------------------------------------------
// helpers
// ---------------------------------------------------------------------------
__device__ __forceinline__ uint32_t smem_u32(const void* p) {
    uint32_t a;
    asm("{ .reg .u64 t; cvta.to.shared.u64 t, %1; cvt.u32.u64 %0, t; }"
        : "=r"(a) : "l"(p));
    return a;
}

#define SWZ(o) ((o) ^ (((o) >> 3) & 0x70))

__device__ __forceinline__ void ldm4(uint32_t* r, uint32_t addr) {
    asm volatile("ldmatrix.sync.aligned.m8n8.x4.shared.b16 {%0,%1,%2,%3}, [%4];"
                 : "=r"(r[0]), "=r"(r[1]), "=r"(r[2]), "=r"(r[3]) : "r"(addr));
}

__device__ __forceinline__ void ldm4t(uint32_t* r, uint32_t addr) {
    asm volatile("ldmatrix.sync.aligned.m8n8.x4.trans.shared.b16 {%0,%1,%2,%3}, [%4];"
                 : "=r"(r[0]), "=r"(r[1]), "=r"(r[2]), "=r"(r[3]) : "r"(addr));
}

// f32-accumulate fp16 mma (main hi*hi pass)
__device__ __forceinline__ void mma_f32(float* c, const uint32_t* a,
                                        uint32_t b0, uint32_t b1) {
    asm volatile(
        "mma.sync.aligned.m16n8k16.row.col.f32.f16.f16.f32 "
        "{%0,%1,%2,%3},{%4,%5,%6,%7},{%8,%9},{%0,%1,%2,%3};"
        : "+f"(c[0]), "+f"(c[1]), "+f"(c[2]), "+f"(c[3])
        : "r"(a[0]), "r"(a[1]), "r"(a[2]), "r"(a[3]), "r"(b0), "r"(b1));
}

// f16-accumulate fp16 mma (correction pass, 2x rate)
__device__ __forceinline__ void mma_f16a(uint32_t* c, const uint32_t* a,
                                         uint32_t b0, uint32_t b1) {
    asm volatile(
        "mma.sync.aligned.m16n8k16.row.col.f16.f16.f16.f16 "
        "{%0,%1},{%2,%3,%4,%5},{%6,%7},{%0,%1};"
        : "+r"(c[0]), "+r"(c[1])
        : "r"(a[0]), "r"(a[1]), "r"(a[2]), "r"(a[3]), "r"(b0), "r"(b1));
}

__device__ __forceinline__ void cp16(uint32_t saddr, const void* gaddr) {
    asm volatile("cp.async.cg.shared.global [%0], [%1], 16;"
                 :: "r"(saddr), "l"(gaddr) : "memory");
}
#define CP_COMMIT() asm volatile("cp.async.commit_group;" ::: "memory")
#define CP_WAIT1()  asm volatile("cp.async.wait_group 1;" ::: "memory")
#define CP_WAIT0()  asm volatile("cp.async.wait_group 0;" ::: "memory")

__device__ __forceinline__ uint32_t b2u(__half2 v) {
    uint32_t u;
    memcpy(&u, &v, 4);
    return u;
}

__device__ __forceinline__ float2 h2f2(uint32_t u) {
    __half2 h;
    memcpy(&h, &u, 4);
    return __half22float2(h);
}

// ---------------------------------------------------------------------------
// fp32 -> fp16 convert of x (A-side hi only)
// ---------------------------------------------------------------------------
__global__ void tohalf_kernel(const float* __restrict__ src,
                              __half* __restrict__ hi, int n4) {
    int i = blockIdx.x * blockDim.x + threadIdx.x;
    if (i >= n4) return;
    float4 v = ((const float4*)src)[i];
    *(__half2*)(hi + 4 * i)     = __floats2half2_rn(v.x, v.y);
    *(__half2*)(hi + 4 * i + 2) = __floats2half2_rn(v.z, v.w);
}

// ---------------------------------------------------------------------------
// RoPE sin/cos table (same powf/sincosf math as verified inline version)
// ---------------------------------------------------------------------------
__global__ void rope_table_kernel(float* __restrict__ tbl) {
    int idx = blockIdx.x * blockDim.x + threadIdx.x;
    if (idx >= SV * 16) return;
    int i = idx & 15, s = idx >> 4;
    float inv = powf(10000.0f, -(float)i / 16.0f);
    float sn, cs;
    sincosf((float)s * inv, &sn, &cs);
    tbl[2 * idx]     = sn;
    tbl[2 * idx + 1] = cs;
}

// ---------------------------------------------------------------------------
// Fused weight transpose + scale + split for all 4 weights (blockIdx.z picks)
// ---------------------------------------------------------------------------
__global__ void trans_split4_kernel(const float* __restrict__ W0,
                                    const float* __restrict__ W1,
                                    const float* __restrict__ W2,
                                    const float* __restrict__ W3,
                                    __half* __restrict__ hi_all,
                                    __half* __restrict__ lo_all) {
    __shared__ float tile[32][33];
    const float* Ws[4] = { W0, W1, W2, W3 };
    const float* W = Ws[blockIdx.z];
    const float scale = (blockIdx.z == 0) ? 0.125f : 1.0f;
    __half* hi = hi_all + (size_t)blockIdx.z * DV * DV;
    __half* lo = lo_all + (size_t)blockIdx.z * DV * DV;

    int bx = blockIdx.x * 32, by = blockIdx.y * 32;
    int tx = threadIdx.x, ty = threadIdx.y;
#pragma unroll
    for (int r = 0; r < 32; r += 8)
        tile[ty + r][tx] = W[(size_t)(by + ty + r) * DV + bx + tx];
    __syncthreads();
#pragma unroll
    for (int r = 0; r < 32; r += 8) {
        float v = tile[tx][ty + r] * scale;
        __half h = __float2half_rn(v);
        size_t o = (size_t)(bx + ty + r) * DV + by + tx;
        hi[o] = h;
        lo[o] = __float2half_rn(v - __half2float(h));
    }
}

// ---------------------------------------------------------------------------
// fp16x2 emulated GEMM: C = Ah @ (Bh + Bl)^T.
// 128x128 block tile, BK=64, 3-stage cp.async pipeline (single barrier per
// iteration), 512 threads (16 warps, 4x4, 32x32 warp tile).
// MODE 0: plain fp32 C output.
// MODE 1: fused QKV epilogue — RoPE + fp16 hi(/lo) split + head-major repack.
// ---------------------------------------------------------------------------
#define GBM 128
#define GBN 128
#define GBK 64
#define TILE_BYTES (GBM * GBK * 2)
#define STAGE_BYTES (3 * TILE_BYTES)      // Ah, Bh, Bl
#define NSTAGE 3
#define GEMM_SMEM (NSTAGE * STAGE_BYTES)  // 147456
#define NITER (DV / GBK)                  // 16

__device__ __forceinline__ void qkv_store(
    int r, int c, float v0, float v1, const float* __restrict__ tbl,
    __half* __restrict__ qh,
    __half* __restrict__ kh, __half* __restrict__ kl,
    __half* __restrict__ vh, __half* __restrict__ vl) {
    const int b = r >> 11, s = r & (SV - 1);
    const int tt = c >> 10;              // 0=q, 1=k, 2=v
    const int cd = c & (DV - 1);
    const int h = cd >> 6, d = cd & (KD - 1);
    if (tt < 2 && d < 32) {
        float2 sc = *(const float2*)(tbl + (size_t)(s * 16 + (d >> 1)) * 2);
        float a = v0 * sc.y - v1 * sc.x;
        float bq = v1 * sc.y + v0 * sc.x;
        v0 = a; v1 = bq;
    }
    const size_t o = (((size_t)(b * HV + h)) * SV + s) * KD + d;
    __half2 hi = __floats2half2_rn(v0, v1);
    if (tt == 0) {
        *(__half2*)(qh + o) = hi;
        return;
    }
    __half2 lo = __floats2half2_rn(v0 - __low2float(hi), v1 - __high2float(hi));
    if (tt == 1) {
        *(__half2*)(kh + o) = hi;
        *(__half2*)(kl + o) = lo;
    } else {
        *(__half2*)(vh + o) = hi;
        *(__half2*)(vl + o) = lo;
    }
}

template <int MODE>
__global__ __launch_bounds__(512, 1)
void mma_gemm(const __half* __restrict__ Ah,
              const __half* __restrict__ Bh,
              const __half* __restrict__ Bl,
              float* __restrict__ C, int ldc,
              const float* __restrict__ tbl,
              __half* __restrict__ qh,
              __half* __restrict__ kh, __half* __restrict__ kl,
              __half* __restrict__ vh, __half* __restrict__ vl) {
    extern __shared__ __align__(1024) char sm[];
    const uint32_t sb = smem_u32(sm);
    const int t = threadIdx.x;
    const int lane = t & 31, wid = t >> 5;
    const int warpM = wid & 3, warpN = wid >> 2;
    const int row0 = blockIdx.y * GBM;
    const int col0 = blockIdx.x * GBN;

    const __half* srcs[3] = {
        Ah + (size_t)row0 * DV,
        Bh + (size_t)col0 * DV, Bl + (size_t)col0 * DV };

    const int cm = t >> 3;        // 0..63
    const int cc = t & 7;

    float accF[2][4][4];
    uint32_t accC[2][4][2];
#pragma unroll
    for (int i = 0; i < 2; i++)
#pragma unroll
        for (int j = 0; j < 4; j++) {
#pragma unroll
            for (int r = 0; r < 4; r++) accF[i][j][r] = 0.0f;
            accC[i][j][0] = 0u; accC[i][j][1] = 0u;
        }

    const int sub = lane >> 3, l7 = lane & 7;
    const int rowA0 = warpM * 32 + ((sub & 1) << 3) + l7;
    const int rowA1 = rowA0 + 16;
    const int kA = (sub >> 1);
    int rowB[2];
#pragma unroll
    for (int p = 0; p < 2; p++)
        rowB[p] = warpN * 32 + p * 16 + ((sub >> 1) << 3) + l7;
    const int kB = (sub & 1);

    // stage issue helper (lambda to keep addressing in one place)
    auto issue = [&](int st) {
        const int k0 = st * GBK;
        const uint32_t stb = sb + (st % NSTAGE) * STAGE_BYTES;
#pragma unroll
        for (int tile = 0; tile < 3; tile++) {
#pragma unroll
            for (int j = 0; j < 2; j++) {
                int m = cm + 64 * j;
                cp16(stb + tile * TILE_BYTES + SWZ(m * 128 + cc * 16),
                     srcs[tile] + (size_t)m * DV + k0 + cc * 8);
            }
        }
        CP_COMMIT();
    };

    issue(0);
    issue(1);

    for (int it = 0; it < NITER; it++) {
        if (it == NITER - 1) { CP_WAIT0(); } else { CP_WAIT1(); }
        __syncthreads();
        if (it + 2 < NITER) issue(it + 2);

        const uint32_t ahB = sb + (it % NSTAGE) * STAGE_BYTES;
        const uint32_t bhB = ahB + TILE_BYTES;
        const uint32_t blB = ahB + 2 * TILE_BYTES;

#pragma unroll
        for (int ks = 0; ks < 4; ks++) {
            const int kcA = ks * 2 + kA;
            const int kcB = ks * 2 + kB;
            uint32_t ah[2][4];
            ldm4(ah[0], ahB + SWZ(rowA0 * 128 + kcA * 16));
            ldm4(ah[1], ahB + SWZ(rowA1 * 128 + kcA * 16));
            uint32_t bh[2][4], bl[2][4];
#pragma unroll
            for (int p = 0; p < 2; p++) {
                ldm4(bh[p], bhB + SWZ(rowB[p] * 128 + kcB * 16));
                ldm4(bl[p], blB + SWZ(rowB[p] * 128 + kcB * 16));
            }
#pragma unroll
            for (int mt = 0; mt < 2; mt++) {
#pragma unroll
                for (int nt = 0; nt < 4; nt++) {
                    const int p = nt >> 1, o = (nt & 1) * 2;
                    mma_f32(accF[mt][nt], ah[mt], bh[p][o], bh[p][o + 1]);
                    mma_f16a(accC[mt][nt], ah[mt], bl[p][o], bl[p][o + 1]);
                }
            }
        }
    }

#pragma unroll
    for (int mt = 0; mt < 2; mt++) {
#pragma unroll
        for (int nt = 0; nt < 4; nt++) {
            float2 c0 = h2f2(accC[mt][nt][0]);
            float2 c1 = h2f2(accC[mt][nt][1]);
            float v0 = accF[mt][nt][0] + c0.x, v1 = accF[mt][nt][1] + c0.y;
            float v2 = accF[mt][nt][2] + c1.x, v3 = accF[mt][nt][3] + c1.y;
            int r = row0 + warpM * 32 + mt * 16 + (lane >> 2);
            int c = col0 + warpN * 32 + nt * 8 + (lane & 3) * 2;
            if (MODE == 0) {
                *(float2*)(C + (size_t)r * ldc + c) = make_float2(v0, v1);
                *(float2*)(C + (size_t)(r + 8) * ldc + c) = make_float2(v2, v3);
            } else {
                qkv_store(r, c, v0, v1, tbl, qh, kh, kl, vh, vl);
                qkv_store(r + 8, c, v2, v3, tbl, qh, kh, kl, vh, vl);
            }
        }
    }
}

// ---------------------------------------------------------------------------
// Tensor-core causal flash attention (unchanged).
// S = Qh*Kh (f32) + Qh*Kl (f16a);  Y = Ph*Vh (f32) + Ph*Vl (f16a).
// grid = (B*H, S/128) with qt reversed (longest CTAs first), 256 threads.
// ---------------------------------------------------------------------------
#define FA_SMEM (16384 + 2 * 65536)

__device__ __forceinline__ void fa_load_kv(
    uint32_t base, const __half* kh, const __half* kl,
    const __half* vh, const __half* vl,
    int kt, int cm, int cc) {
    const __half* srcs[4] = { kh, kl, vh, vl };
#pragma unroll
    for (int tt = 0; tt < 4; tt++) {
#pragma unroll
        for (int j = 0; j < 4; j++) {
            int r = cm + 32 * j;
            cp16(base + tt * 16384 + SWZ(r * 128 + cc * 16),
                 srcs[tt] + (size_t)(kt * 128 + r) * KD + cc * 8);
        }
    }
    CP_COMMIT();
}

__global__ __launch_bounds__(256, 1)
void flash_mma(const __half* __restrict__ qh,
               const __half* __restrict__ kh, const __half* __restrict__ kl,
               const __half* __restrict__ vh, const __half* __restrict__ vl,
               __half* __restrict__ yhp) {
    extern __shared__ __align__(1024) char sm[];
    const uint32_t sb = smem_u32(sm);
    const int t = threadIdx.x, lane = t & 31, w = t >> 5;
    const int bh = blockIdx.x;
    const int qt = (int)gridDim.y - 1 - (int)blockIdx.y;   // longest first
    const size_t ho = (size_t)bh * SV * KD;

    const int cm = t >> 3, cc = t & 7;

    {
        const __half* qsrc = qh + ho + (size_t)qt * 128 * KD;
#pragma unroll
        for (int j = 0; j < 4; j++) {
            int r = cm + 32 * j;
            cp16(sb + SWZ(r * 128 + cc * 16), qsrc + (size_t)r * KD + cc * 8);
        }
        CP_COMMIT();
    }
    fa_load_kv(sb + 16384, kh + ho, kl + ho, vh + ho, vl + ho, 0, cm, cc);

    const int nt = qt + 1;
    const int sub = lane >> 3, l7 = lane & 7;

    uint32_t qfh[4][4];
    float m0 = -3.0e38f, m1 = -3.0e38f, l0 = 0.0f, l1 = 0.0f;
    float yacc[8][4];
#pragma unroll
    for (int p = 0; p < 8; p++)
#pragma unroll
        for (int e = 0; e < 4; e++) yacc[p][e] = 0.0f;

    for (int kt = 0; kt < nt; kt++) {
        const int st = kt & 1;
        CP_WAIT0();
        __syncthreads();

        if (kt == 0) {
            const int rA = w * 16 + ((sub & 1) << 3) + l7;
            const int kA = sub >> 1;
#pragma unroll
            for (int kc = 0; kc < 4; kc++)
                ldm4(qfh[kc], sb + SWZ(rA * 128 + (kc * 2 + kA) * 16));
        }
        if (kt + 1 < nt)
            fa_load_kv(sb + 16384 + (st ^ 1) * 65536,
                       kh + ho, kl + ho, vh + ho, vl + ho, kt + 1, cm, cc);

        const uint32_t KhB = sb + 16384 + st * 65536;
        const uint32_t KlB = KhB + 16384;
        const uint32_t VhB = KhB + 32768;
        const uint32_t VlB = KhB + 49152;

        // ---- S = Q K^T ----
        float sacc[16][4];
        uint32_t cacc[16][2];
#pragma unroll
        for (int n8 = 0; n8 < 16; n8++) {
#pragma unroll
            for (int e = 0; e < 4; e++) sacc[n8][e] = 0.0f;
            cacc[n8][0] = 0u; cacc[n8][1] = 0u;
        }

        const int rB = ((sub >> 1) << 3) + l7;
        const int kB = sub & 1;
#pragma unroll
        for (int kc = 0; kc < 4; kc++) {
#pragma unroll
            for (int p = 0; p < 8; p++) {
                uint32_t off = SWZ((p * 16 + rB) * 128 + (kc * 2 + kB) * 16);
                uint32_t kh4[4], kl4[4];
                ldm4(kh4, KhB + off);
                ldm4(kl4, KlB + off);
                mma_f32(sacc[2 * p], qfh[kc], kh4[0], kh4[1]);
                mma_f16a(cacc[2 * p], qfh[kc], kl4[0], kl4[1]);
                mma_f32(sacc[2 * p + 1], qfh[kc], kh4[2], kh4[3]);
                mma_f16a(cacc[2 * p + 1], qfh[kc], kl4[2], kl4[3]);
            }
        }
#pragma unroll
        for (int n8 = 0; n8 < 16; n8++) {
            float2 c0 = h2f2(cacc[n8][0]);
            float2 c1 = h2f2(cacc[n8][1]);
            sacc[n8][0] += c0.x; sacc[n8][1] += c0.y;
            sacc[n8][2] += c1.x; sacc[n8][3] += c1.y;
        }

        // causal mask on diagonal tile
        const int rr0 = w * 16 + (lane >> 2);
        if (kt == qt) {
#pragma unroll
            for (int n8 = 0; n8 < 16; n8++) {
                int cb = n8 * 8 + (lane & 3) * 2;
                if (cb     > rr0)     sacc[n8][0] = -1e30f;
                if (cb + 1 > rr0)     sacc[n8][1] = -1e30f;
                if (cb     > rr0 + 8) sacc[n8][2] = -1e30f;
                if (cb + 1 > rr0 + 8) sacc[n8][3] = -1e30f;
            }
        }

        // ---- online softmax ----
        float mx0 = -3.0e38f, mx1 = -3.0e38f;
#pragma unroll
        for (int n8 = 0; n8 < 16; n8++) {
            mx0 = fmaxf(mx0, fmaxf(sacc[n8][0], sacc[n8][1]));
            mx1 = fmaxf(mx1, fmaxf(sacc[n8][2], sacc[n8][3]));
        }
        mx0 = fmaxf(mx0, __shfl_xor_sync(0xffffffffu, mx0, 1));
        mx0 = fmaxf(mx0, __shfl_xor_sync(0xffffffffu, mx0, 2));
        mx1 = fmaxf(mx1, __shfl_xor_sync(0xffffffffu, mx1, 1));
        mx1 = fmaxf(mx1, __shfl_xor_sync(0xffffffffu, mx1, 2));
        const float mt0 = fmaxf(m0, mx0), mt1 = fmaxf(m1, mx1);
        const float sc0 = __expf(m0 - mt0), sc1 = __expf(m1 - mt1);
        l0 *= sc0; l1 *= sc1;
#pragma unroll
        for (int p = 0; p < 8; p++) {
            yacc[p][0] *= sc0; yacc[p][1] *= sc0;
            yacc[p][2] *= sc1; yacc[p][3] *= sc1;
        }
        m0 = mt0; m1 = mt1;

        // p = exp(s - m) -> fp16 A-fragments (hi only)
        uint32_t aH[8][4];
        float rs0 = 0.0f, rs1 = 0.0f;
#pragma unroll
        for (int kc = 0; kc < 8; kc++) {
#pragma unroll
            for (int e = 0; e < 2; e++) {
                const int n8 = 2 * kc + e;
                float p0 = __expf(sacc[n8][0] - mt0);
                float p1 = __expf(sacc[n8][1] - mt0);
                float p2 = __expf(sacc[n8][2] - mt1);
                float p3 = __expf(sacc[n8][3] - mt1);
                rs0 += p0 + p1; rs1 += p2 + p3;
                aH[kc][2 * e]     = b2u(__floats2half2_rn(p0, p1));
                aH[kc][2 * e + 1] = b2u(__floats2half2_rn(p2, p3));
            }
        }
        rs0 += __shfl_xor_sync(0xffffffffu, rs0, 1);
        rs0 += __shfl_xor_sync(0xffffffffu, rs0, 2);
        rs1 += __shfl_xor_sync(0xffffffffu, rs1, 1);
        rs1 += __shfl_xor_sync(0xffffffffu, rs1, 2);
        l0 += rs0; l1 += rs1;

        // ---- Y += P V ----
        uint32_t ycc[8][2];
#pragma unroll
        for (int p = 0; p < 8; p++) { ycc[p][0] = 0u; ycc[p][1] = 0u; }

        const int vr = ((lane >> 3) & 1) * 8 + (lane & 7);
        const int vc = (lane >> 4) * 8;
#pragma unroll
        for (int kc = 0; kc < 8; kc++) {
#pragma unroll
            for (int p = 0; p < 4; p++) {
                uint32_t off = SWZ((kc * 16 + vr) * 128 + (p * 16 + vc) * 2);
                uint32_t vh4[4], vl4[4];
                ldm4t(vh4, VhB + off);
                ldm4t(vl4, VlB + off);
                mma_f32(yacc[2 * p], aH[kc], vh4[0], vh4[1]);
                mma_f16a(ycc[2 * p], aH[kc], vl4[0], vl4[1]);
                mma_f32(yacc[2 * p + 1], aH[kc], vh4[2], vh4[3]);
                mma_f16a(ycc[2 * p + 1], aH[kc], vl4[2], vl4[3]);
            }
        }
#pragma unroll
        for (int p = 0; p < 8; p++) {
            float2 c0 = h2f2(ycc[p][0]);
            float2 c1 = h2f2(ycc[p][1]);
            yacc[p][0] += c0.x; yacc[p][1] += c0.y;
            yacc[p][2] += c1.x; yacc[p][3] += c1.y;
        }
        __syncthreads();
    }

    // epilogue: normalize, fp16 convert, write [B,S,D]
    const float il0 = 1.0f / l0, il1 = 1.0f / l1;
    const int b = bh / HV, h = bh % HV;
    const int gr0 = qt * 128 + w * 16 + (lane >> 2);
    const size_t o0 = ((size_t)(b * SV) + gr0) * DV + h * KD;
    const size_t o1 = o0 + (size_t)8 * DV;
#pragma unroll
    for (int p = 0; p < 8; p++) {
        int c = p * 8 + (lane & 3) * 2;
        *(__half2*)(yhp + o0 + c) = __floats2half2_rn(yacc[p][0] * il0, yacc[p][1] * il0);
        *(__half2*)(yhp + o1 + c) = __floats2half2_rn(yacc[p][2] * il1, yacc[p][3] * il1);
    }
}

// ---------------------------------------------------------------------------
// kernel_launch
// ---------------------------------------------------------------------------
extern "C" void kernel_launch(void* const* d_in, const int* in_sizes, int n_in,
                              void* d_out, int out_size) {
    (void)in_sizes; (void)n_in; (void)out_size;
    const float* x  = (const float*)d_in[0];
    const float* Wq = (const float*)d_in[2];
    const float* Wk = (const float*)d_in[3];
    const float* Wv = (const float*)d_in[4];
    const float* Wo = (const float*)d_in[5];
    float* out = (float*)d_out;

    float* tbl;
    __half *xh, *wh, *wl, *qh, *kh, *kl, *vh, *vl, *yh;
    cudaGetSymbolAddress((void**)&tbl, g_rope);
    cudaGetSymbolAddress((void**)&xh, g_xh);
    cudaGetSymbolAddress((void**)&wh, g_wh);
    cudaGetSymbolAddress((void**)&wl, g_wl);
    cudaGetSymbolAddress((void**)&qh, g_qh);
    cudaGetSymbolAddress((void**)&kh, g_kh);
    cudaGetSymbolAddress((void**)&kl, g_kl);
    cudaGetSymbolAddress((void**)&vh, g_vh);
    cudaGetSymbolAddress((void**)&vl, g_vl);
    cudaGetSymbolAddress((void**)&yh, g_yh);

    cudaFuncSetAttribute(mma_gemm<0>, cudaFuncAttributeMaxDynamicSharedMemorySize, GEMM_SMEM);
    cudaFuncSetAttribute(mma_gemm<1>, cudaFuncAttributeMaxDynamicSharedMemorySize, GEMM_SMEM);
    cudaFuncSetAttribute(flash_mma, cudaFuncAttributeMaxDynamicSharedMemorySize, FA_SMEM);

    int n4 = MROWS * DV / 4;
    tohalf_kernel<<<(n4 + 255) / 256, 256>>>(x, xh, n4);

    dim3 tgrid(DV / 32, DV / 32, 4);
    dim3 tblk(32, 8);
    trans_split4_kernel<<<tgrid, tblk>>>(Wq, Wk, Wv, Wo, wh, wl);

    rope_table_kernel<<<(SV * 16 + 255) / 256, 256>>>(tbl);

    // fused QKV projection (N = 3072) with fused rope/split/repack epilogue
    dim3 qkvgrid(3 * DV / GBN, MROWS / GBM);   // (24, 32)
    mma_gemm<1><<<qkvgrid, 512, GEMM_SMEM>>>(xh, wh, wl, nullptr, 0,
                                             tbl, qh, kh, kl, vh, vl);

    // tensor-core flash attention (longest CTAs scheduled first)
    dim3 fgrid(BV * HV, SV / 128);             // (32, 16)
    flash_mma<<<fgrid, 256, FA_SMEM>>>(qh, kh, kl, vh, vl, yh);

    // output projection
    dim3 ogrid(DV / GBN, MROWS / GBM);         // (8, 32)
    mma_gemm<0><<<ogrid, 512, GEMM_SMEM>>>(yh, wh + 3 * (size_t)DV * DV,
                                           wl + 3 * (size_t)DV * DV, out, DV,
                                           nullptr, nullptr, nullptr, nullptr,
                                           nullptr, nullptr);
}

// round 9
// speedup vs baseline: 10.0606x; 1.7456x over previous
#include <cuda_runtime.h>
#include <cuda_fp16.h>
#include <math.h>
#include <stdint.h>
#include <string.h>

// ---------------------------------------------------------------------------
// Problem constants: B=2, S=2048, D=1024, H=16, head_dim=64, rope dims=32
// ---------------------------------------------------------------------------
#define BV 2
#define HV 16
#define SV 2048
#define DV 1024
#define KD 64
#define MROWS (BV*SV)        // 4096
#define HEADROWS (BV*HV*SV)  // 65536

// Scratch (device globals: allocation-free rule)
__device__ float g_rope[SV * 16 * 2];     // (sin, cos) per (s, pair)
__device__ __half g_xh[MROWS * DV];
__device__ __half g_wh[4 * DV * DV];
__device__ __half g_qh[HEADROWS * KD];
__device__ __half g_kh[HEADROWS * KD];
__device__ __half g_vh[HEADROWS * KD];
__device__ __half g_yh[MROWS * DV];

// ---------------------------------------------------------------------------
// helpers
// ---------------------------------------------------------------------------
__device__ __forceinline__ uint32_t smem_u32(const void* p) {
    uint32_t a;
    asm("{ .reg .u64 t; cvta.to.shared.u64 t, %1; cvt.u32.u64 %0, t; }"
        : "=r"(a) : "l"(p));
    return a;
}

#define SWZ(o) ((o) ^ (((o) >> 3) & 0x70))

__device__ __forceinline__ void ldm4(uint32_t* r, uint32_t addr) {
    asm volatile("ldmatrix.sync.aligned.m8n8.x4.shared.b16 {%0,%1,%2,%3}, [%4];"
                 : "=r"(r[0]), "=r"(r[1]), "=r"(r[2]), "=r"(r[3]) : "r"(addr));
}

__device__ __forceinline__ void ldm4t(uint32_t* r, uint32_t addr) {
    asm volatile("ldmatrix.sync.aligned.m8n8.x4.trans.shared.b16 {%0,%1,%2,%3}, [%4];"
                 : "=r"(r[0]), "=r"(r[1]), "=r"(r[2]), "=r"(r[3]) : "r"(addr));
}

// f32-accumulate fp16 mma
__device__ __forceinline__ void mma_f32(float* c, const uint32_t* a,
                                        uint32_t b0, uint32_t b1) {
    asm volatile(
        "mma.sync.aligned.m16n8k16.row.col.f32.f16.f16.f32 "
        "{%0,%1,%2,%3},{%4,%5,%6,%7},{%8,%9},{%0,%1,%2,%3};"
        : "+f"(c[0]), "+f"(c[1]), "+f"(c[2]), "+f"(c[3])
        : "r"(a[0]), "r"(a[1]), "r"(a[2]), "r"(a[3]), "r"(b0), "r"(b1));
}

__device__ __forceinline__ void cp16(uint32_t saddr, const void* gaddr) {
    asm volatile("cp.async.cg.shared.global [%0], [%1], 16;"
                 :: "r"(saddr), "l"(gaddr) : "memory");
}
#define CP_COMMIT() asm volatile("cp.async.commit_group;" ::: "memory")
#define CP_WAIT1()  asm volatile("cp.async.wait_group 1;" ::: "memory")
#define CP_WAIT0()  asm volatile("cp.async.wait_group 0;" ::: "memory")

__device__ __forceinline__ uint32_t b2u(__half2 v) {
    uint32_t u;
    memcpy(&u, &v, 4);
    return u;
}

// ---------------------------------------------------------------------------
// fp32 -> fp16 convert of x
// ---------------------------------------------------------------------------
__global__ void tohalf_kernel(const float* __restrict__ src,
                              __half* __restrict__ hi, int n4) {
    int i = blockIdx.x * blockDim.x + threadIdx.x;
    if (i >= n4) return;
    float4 v = ((const float4*)src)[i];
    *(__half2*)(hi + 4 * i)     = __floats2half2_rn(v.x, v.y);
    *(__half2*)(hi + 4 * i + 2) = __floats2half2_rn(v.z, v.w);
}

// ---------------------------------------------------------------------------
// RoPE sin/cos table (same powf/sincosf math as verified inline version)
// ---------------------------------------------------------------------------
__global__ void rope_table_kernel(float* __restrict__ tbl) {
    int idx = blockIdx.x * blockDim.x + threadIdx.x;
    if (idx >= SV * 16) return;
    int i = idx & 15, s = idx >> 4;
    float inv = powf(10000.0f, -(float)i / 16.0f);
    float sn, cs;
    sincosf((float)s * inv, &sn, &cs);
    tbl[2 * idx]     = sn;
    tbl[2 * idx + 1] = cs;
}

// ---------------------------------------------------------------------------
// Fused weight transpose + scale + fp16 convert for all 4 weights
// ---------------------------------------------------------------------------
__global__ void trans4_kernel(const float* __restrict__ W0,
                              const float* __restrict__ W1,
                              const float* __restrict__ W2,
                              const float* __restrict__ W3,
                              __half* __restrict__ hi_all) {
    __shared__ float tile[32][33];
    const float* Ws[4] = { W0, W1, W2, W3 };
    const float* W = Ws[blockIdx.z];
    const float scale = (blockIdx.z == 0) ? 0.125f : 1.0f;
    __half* hi = hi_all + (size_t)blockIdx.z * DV * DV;

    int bx = blockIdx.x * 32, by = blockIdx.y * 32;
    int tx = threadIdx.x, ty = threadIdx.y;
#pragma unroll
    for (int r = 0; r < 32; r += 8)
        tile[ty + r][tx] = W[(size_t)(by + ty + r) * DV + bx + tx];
    __syncthreads();
#pragma unroll
    for (int r = 0; r < 32; r += 8) {
        float v = tile[tx][ty + r] * scale;
        hi[(size_t)(bx + ty + r) * DV + by + tx] = __float2half_rn(v);
    }
}

// ---------------------------------------------------------------------------
// fp16 GEMM (f32 accumulate): C = Ah @ Bh^T.
// 128x128 block tile, BK=64, 3-stage cp.async pipeline, 512 threads
// (16 warps, 4x4, 32x32 warp tile).
// MODE 0: plain fp32 C output.
// MODE 1: fused QKV epilogue — RoPE + fp16 convert + head-major repack.
// ---------------------------------------------------------------------------
#define GBM 128
#define GBN 128
#define GBK 64
#define TILE_BYTES (GBM * GBK * 2)
#define STAGE_BYTES (2 * TILE_BYTES)      // Ah, Bh
#define NSTAGE 3
#define GEMM_SMEM (NSTAGE * STAGE_BYTES)  // 98304
#define NITER (DV / GBK)                  // 16

__device__ __forceinline__ void qkv_store(
    int r, int c, float v0, float v1, const float* __restrict__ tbl,
    __half* __restrict__ qh, __half* __restrict__ kh, __half* __restrict__ vh) {
    const int b = r >> 11, s = r & (SV - 1);
    const int tt = c >> 10;              // 0=q, 1=k, 2=v
    const int cd = c & (DV - 1);
    const int h = cd >> 6, d = cd & (KD - 1);
    if (tt < 2 && d < 32) {
        float2 sc = *(const float2*)(tbl + (size_t)(s * 16 + (d >> 1)) * 2);
        float a = v0 * sc.y - v1 * sc.x;
        float bq = v1 * sc.y + v0 * sc.x;
        v0 = a; v1 = bq;
    }
    const size_t o = (((size_t)(b * HV + h)) * SV + s) * KD + d;
    __half* dst = (tt == 0) ? qh : (tt == 1) ? kh : vh;
    *(__half2*)(dst + o) = __floats2half2_rn(v0, v1);
}

template <int MODE>
__global__ __launch_bounds__(512, 1)
void mma_gemm(const __half* __restrict__ Ah,
              const __half* __restrict__ Bh,
              float* __restrict__ C, int ldc,
              const float* __restrict__ tbl,
              __half* __restrict__ qh, __half* __restrict__ kh,
              __half* __restrict__ vh) {
    extern __shared__ __align__(1024) char sm[];
    const uint32_t sb = smem_u32(sm);
    const int t = threadIdx.x;
    const int lane = t & 31, wid = t >> 5;
    const int warpM = wid & 3, warpN = wid >> 2;
    const int row0 = blockIdx.y * GBM;
    const int col0 = blockIdx.x * GBN;

    const __half* srcs[2] = { Ah + (size_t)row0 * DV, Bh + (size_t)col0 * DV };

    const int cm = t >> 3;        // 0..63
    const int cc = t & 7;

    float accF[2][4][4];
#pragma unroll
    for (int i = 0; i < 2; i++)
#pragma unroll
        for (int j = 0; j < 4; j++)
#pragma unroll
            for (int r = 0; r < 4; r++) accF[i][j][r] = 0.0f;

    const int sub = lane >> 3, l7 = lane & 7;
    const int rowA0 = warpM * 32 + ((sub & 1) << 3) + l7;
    const int rowA1 = rowA0 + 16;
    const int kA = (sub >> 1);
    int rowB[2];
#pragma unroll
    for (int p = 0; p < 2; p++)
        rowB[p] = warpN * 32 + p * 16 + ((sub >> 1) << 3) + l7;
    const int kB = (sub & 1);

    auto issue = [&](int st) {
        const int k0 = st * GBK;
        const uint32_t stb = sb + (st % NSTAGE) * STAGE_BYTES;
#pragma unroll
        for (int tile = 0; tile < 2; tile++) {
#pragma unroll
            for (int j = 0; j < 2; j++) {
                int m = cm + 64 * j;
                cp16(stb + tile * TILE_BYTES + SWZ(m * 128 + cc * 16),
                     srcs[tile] + (size_t)m * DV + k0 + cc * 8);
            }
        }
        CP_COMMIT();
    };

    issue(0);
    issue(1);

    for (int it = 0; it < NITER; it++) {
        if (it == NITER - 1) { CP_WAIT0(); } else { CP_WAIT1(); }
        __syncthreads();
        if (it + 2 < NITER) issue(it + 2);

        const uint32_t ahB = sb + (it % NSTAGE) * STAGE_BYTES;
        const uint32_t bhB = ahB + TILE_BYTES;

#pragma unroll
        for (int ks = 0; ks < 4; ks++) {
            const int kcA = ks * 2 + kA;
            const int kcB = ks * 2 + kB;
            uint32_t ah[2][4];
            ldm4(ah[0], ahB + SWZ(rowA0 * 128 + kcA * 16));
            ldm4(ah[1], ahB + SWZ(rowA1 * 128 + kcA * 16));
            uint32_t bh[2][4];
#pragma unroll
            for (int p = 0; p < 2; p++)
                ldm4(bh[p], bhB + SWZ(rowB[p] * 128 + kcB * 16));
#pragma unroll
            for (int mt = 0; mt < 2; mt++) {
#pragma unroll
                for (int nt = 0; nt < 4; nt++) {
                    const int p = nt >> 1, o = (nt & 1) * 2;
                    mma_f32(accF[mt][nt], ah[mt], bh[p][o], bh[p][o + 1]);
                }
            }
        }
    }

#pragma unroll
    for (int mt = 0; mt < 2; mt++) {
#pragma unroll
        for (int nt = 0; nt < 4; nt++) {
            float v0 = accF[mt][nt][0], v1 = accF[mt][nt][1];
            float v2 = accF[mt][nt][2], v3 = accF[mt][nt][3];
            int r = row0 + warpM * 32 + mt * 16 + (lane >> 2);
            int c = col0 + warpN * 32 + nt * 8 + (lane & 3) * 2;
            if (MODE == 0) {
                *(float2*)(C + (size_t)r * ldc + c) = make_float2(v0, v1);
                *(float2*)(C + (size_t)(r + 8) * ldc + c) = make_float2(v2, v3);
            } else {
                qkv_store(r, c, v0, v1, tbl, qh, kh, vh);
                qkv_store(r + 8, c, v2, v3, tbl, qh, kh, vh);
            }
        }
    }
}

// ---------------------------------------------------------------------------
// Tensor-core causal flash attention, pure fp16 operands / fp32 accum.
// grid = (B*H, S/128) with qt reversed (longest CTAs first), 256 threads.
// SMEM: Qh (16KB) + 2-stage {Kh,Vh} (2x32KB) = 80KB.
// ---------------------------------------------------------------------------
#define FA_STAGE 32768
#define FA_SMEM (16384 + 2 * FA_STAGE)

__device__ __forceinline__ void fa_load_kv(
    uint32_t base, const __half* kh, const __half* vh,
    int kt, int cm, int cc) {
    const __half* srcs[2] = { kh, vh };
#pragma unroll
    for (int tt = 0; tt < 2; tt++) {
#pragma unroll
        for (int j = 0; j < 4; j++) {
            int r = cm + 32 * j;
            cp16(base + tt * 16384 + SWZ(r * 128 + cc * 16),
                 srcs[tt] + (size_t)(kt * 128 + r) * KD + cc * 8);
        }
    }
    CP_COMMIT();
}

__global__ __launch_bounds__(256, 1)
void flash_mma(const __half* __restrict__ qh,
               const __half* __restrict__ kh, const __half* __restrict__ vh,
               __half* __restrict__ yhp) {
    extern __shared__ __align__(1024) char sm[];
    const uint32_t sb = smem_u32(sm);
    const int t = threadIdx.x, lane = t & 31, w = t >> 5;
    const int bh = blockIdx.x;
    const int qt = (int)gridDim.y - 1 - (int)blockIdx.y;   // longest first
    const size_t ho = (size_t)bh * SV * KD;

    const int cm = t >> 3, cc = t & 7;

    {
        const __half* qsrc = qh + ho + (size_t)qt * 128 * KD;
#pragma unroll
        for (int j = 0; j < 4; j++) {
            int r = cm + 32 * j;
            cp16(sb + SWZ(r * 128 + cc * 16), qsrc + (size_t)r * KD + cc * 8);
        }
        CP_COMMIT();
    }
    fa_load_kv(sb + 16384, kh + ho, vh + ho, 0, cm, cc);

    const int nt = qt + 1;
    const int sub = lane >> 3, l7 = lane & 7;

    uint32_t qfh[4][4];
    float m0 = -3.0e38f, m1 = -3.0e38f, l0 = 0.0f, l1 = 0.0f;
    float yacc[8][4];
#pragma unroll
    for (int p = 0; p < 8; p++)
#pragma unroll
        for (int e = 0; e < 4; e++) yacc[p][e] = 0.0f;

    for (int kt = 0; kt < nt; kt++) {
        const int st = kt & 1;
        CP_WAIT0();
        __syncthreads();

        if (kt == 0) {
            const int rA = w * 16 + ((sub & 1) << 3) + l7;
            const int kA = sub >> 1;
#pragma unroll
            for (int kc = 0; kc < 4; kc++)
                ldm4(qfh[kc], sb + SWZ(rA * 128 + (kc * 2 + kA) * 16));
        }
        if (kt + 1 < nt)
            fa_load_kv(sb + 16384 + (st ^ 1) * FA_STAGE,
                       kh + ho, vh + ho, kt + 1, cm, cc);

        const uint32_t KhB = sb + 16384 + st * FA_STAGE;
        const uint32_t VhB = KhB + 16384;

        // ---- S = Q K^T ----
        float sacc[16][4];
#pragma unroll
        for (int n8 = 0; n8 < 16; n8++)
#pragma unroll
            for (int e = 0; e < 4; e++) sacc[n8][e] = 0.0f;

        const int rB = ((sub >> 1) << 3) + l7;
        const int kB = sub & 1;
#pragma unroll
        for (int kc = 0; kc < 4; kc++) {
#pragma unroll
            for (int p = 0; p < 8; p++) {
                uint32_t off = SWZ((p * 16 + rB) * 128 + (kc * 2 + kB) * 16);
                uint32_t kh4[4];
                ldm4(kh4, KhB + off);
                mma_f32(sacc[2 * p], qfh[kc], kh4[0], kh4[1]);
                mma_f32(sacc[2 * p + 1], qfh[kc], kh4[2], kh4[3]);
            }
        }

        // causal mask on diagonal tile
        const int rr0 = w * 16 + (lane >> 2);
        if (kt == qt) {
#pragma unroll
            for (int n8 = 0; n8 < 16; n8++) {
                int cb = n8 * 8 + (lane & 3) * 2;
                if (cb     > rr0)     sacc[n8][0] = -1e30f;
                if (cb + 1 > rr0)     sacc[n8][1] = -1e30f;
                if (cb     > rr0 + 8) sacc[n8][2] = -1e30f;
                if (cb + 1 > rr0 + 8) sacc[n8][3] = -1e30f;
            }
        }

        // ---- online softmax ----
        float mx0 = -3.0e38f, mx1 = -3.0e38f;
#pragma unroll
        for (int n8 = 0; n8 < 16; n8++) {
            mx0 = fmaxf(mx0, fmaxf(sacc[n8][0], sacc[n8][1]));
            mx1 = fmaxf(mx1, fmaxf(sacc[n8][2], sacc[n8][3]));
        }
        mx0 = fmaxf(mx0, __shfl_xor_sync(0xffffffffu, mx0, 1));
        mx0 = fmaxf(mx0, __shfl_xor_sync(0xffffffffu, mx0, 2));
        mx1 = fmaxf(mx1, __shfl_xor_sync(0xffffffffu, mx1, 1));
        mx1 = fmaxf(mx1, __shfl_xor_sync(0xffffffffu, mx1, 2));
        const float mt0 = fmaxf(m0, mx0), mt1 = fmaxf(m1, mx1);
        const float sc0 = __expf(m0 - mt0), sc1 = __expf(m1 - mt1);
        l0 *= sc0; l1 *= sc1;
#pragma unroll
        for (int p = 0; p < 8; p++) {
            yacc[p][0] *= sc0; yacc[p][1] *= sc0;
            yacc[p][2] *= sc1; yacc[p][3] *= sc1;
        }
        m0 = mt0; m1 = mt1;

        // p = exp(s - m) -> fp16 A-fragments
        uint32_t aH[8][4];
        float rs0 = 0.0f, rs1 = 0.0f;
#pragma unroll
        for (int kc = 0; kc < 8; kc++) {
#pragma unroll
            for (int e = 0; e < 2; e++) {
                const int n8 = 2 * kc + e;
                float p0 = __expf(sacc[n8][0] - mt0);
                float p1 = __expf(sacc[n8][1] - mt0);
                float p2 = __expf(sacc[n8][2] - mt1);
                float p3 = __expf(sacc[n8][3] - mt1);
                rs0 += p0 + p1; rs1 += p2 + p3;
                aH[kc][2 * e]     = b2u(__floats2half2_rn(p0, p1));
                aH[kc][2 * e + 1] = b2u(__floats2half2_rn(p2, p3));
            }
        }
        rs0 += __shfl_xor_sync(0xffffffffu, rs0, 1);
        rs0 += __shfl_xor_sync(0xffffffffu, rs0, 2);
        rs1 += __shfl_xor_sync(0xffffffffu, rs1, 1);
        rs1 += __shfl_xor_sync(0xffffffffu, rs1, 2);
        l0 += rs0; l1 += rs1;

        // ---- Y += P V ----
        const int vr = ((lane >> 3) & 1) * 8 + (lane & 7);
        const int vc = (lane >> 4) * 8;
#pragma unroll
        for (int kc = 0; kc < 8; kc++) {
#pragma unroll
            for (int p = 0; p < 4; p++) {
                uint32_t off = SWZ((kc * 16 + vr) * 128 + (p * 16 + vc) * 2);
                uint32_t vh4[4];
                ldm4t(vh4, VhB + off);
                mma_f32(yacc[2 * p], aH[kc], vh4[0], vh4[1]);
                mma_f32(yacc[2 * p + 1], aH[kc], vh4[2], vh4[3]);
            }
        }
        __syncthreads();
    }

    // epilogue: normalize, fp16 convert, write [B,S,D]
    const float il0 = 1.0f / l0, il1 = 1.0f / l1;
    const int b = bh / HV, h = bh % HV;
    const int gr0 = qt * 128 + w * 16 + (lane >> 2);
    const size_t o0 = ((size_t)(b * SV) + gr0) * DV + h * KD;
    const size_t o1 = o0 + (size_t)8 * DV;
#pragma unroll
    for (int p = 0; p < 8; p++) {
        int c = p * 8 + (lane & 3) * 2;
        *(__half2*)(yhp + o0 + c) = __floats2half2_rn(yacc[p][0] * il0, yacc[p][1] * il0);
        *(__half2*)(yhp + o1 + c) = __floats2half2_rn(yacc[p][2] * il1, yacc[p][3] * il1);
    }
}

// ---------------------------------------------------------------------------
// kernel_launch
// ---------------------------------------------------------------------------
extern "C" void kernel_launch(void* const* d_in, const int* in_sizes, int n_in,
                              void* d_out, int out_size) {
    (void)in_sizes; (void)n_in; (void)out_size;
    const float* x  = (const float*)d_in[0];
    const float* Wq = (const float*)d_in[2];
    const float* Wk = (const float*)d_in[3];
    const float* Wv = (const float*)d_in[4];
    const float* Wo = (const float*)d_in[5];
    float* out = (float*)d_out;

    float* tbl;
    __half *xh, *wh, *qh, *kh, *vh, *yh;
    cudaGetSymbolAddress((void**)&tbl, g_rope);
    cudaGetSymbolAddress((void**)&xh, g_xh);
    cudaGetSymbolAddress((void**)&wh, g_wh);
    cudaGetSymbolAddress((void**)&qh, g_qh);
    cudaGetSymbolAddress((void**)&kh, g_kh);
    cudaGetSymbolAddress((void**)&vh, g_vh);
    cudaGetSymbolAddress((void**)&yh, g_yh);

    cudaFuncSetAttribute(mma_gemm<0>, cudaFuncAttributeMaxDynamicSharedMemorySize, GEMM_SMEM);
    cudaFuncSetAttribute(mma_gemm<1>, cudaFuncAttributeMaxDynamicSharedMemorySize, GEMM_SMEM);
    cudaFuncSetAttribute(flash_mma, cudaFuncAttributeMaxDynamicSharedMemorySize, FA_SMEM);

    int n4 = MROWS * DV / 4;
    tohalf_kernel<<<(n4 + 255) / 256, 256>>>(x, xh, n4);

    dim3 tgrid(DV / 32, DV / 32, 4);
    dim3 tblk(32, 8);
    trans4_kernel<<<tgrid, tblk>>>(Wq, Wk, Wv, Wo, wh);

    rope_table_kernel<<<(SV * 16 + 255) / 256, 256>>>(tbl);

    // fused QKV projection (N = 3072) with fused rope/repack epilogue
    dim3 qkvgrid(3 * DV / GBN, MROWS / GBM);   // (24, 32)
    mma_gemm<1><<<qkvgrid, 512, GEMM_SMEM>>>(xh, wh, nullptr, 0,
                                             tbl, qh, kh, vh);

    // tensor-core flash attention (longest CTAs scheduled first)
    dim3 fgrid(BV * HV, SV / 128);             // (32, 16)
    flash_mma<<<fgrid, 256, FA_SMEM>>>(qh, kh, vh, yh);

    // output projection
    dim3 ogrid(DV / GBN, MROWS / GBM);         // (8, 32)
    mma_gemm<0><<<ogrid, 512, GEMM_SMEM>>>(yh, wh + 3 * (size_t)DV * DV,
                                           out, DV,
                                           nullptr, nullptr, nullptr, nullptr);
}